// round 8
// baseline (speedup 1.0000x reference)
#include <cuda_runtime.h>
#include <cuda_bf16.h>
#include <cstdint>
#include <math.h>

// Problem constants
#define Bq   8
#define Sq   1024
#define Dq   512
#define Hq   8
#define DHq  64
#define BSr  (Bq*Sq)        // 8192 rows
#define BSD  (Bq*Sq*Dq)     // 4194304 elements

// ---------------- device scratch (no allocations allowed) ----------------
__device__ float g_E [BSD];
__device__ float g_DI[BSD];
__device__ float g_S [BSD];
__device__ float g_I [BSD];
__device__ float g_EO[BSD];
__device__ __nv_bfloat16 g_Ahi[BSD], g_Alo[BSD];
__device__ __nv_bfloat16 g_Qhi[BSD], g_Qlo[BSD];
__device__ __nv_bfloat16 g_Khi[BSD], g_Klo[BSD];
__device__ __nv_bfloat16 g_Vhi[BSD], g_Vlo[BSD];
__device__ __nv_bfloat16 g_EOhi[BSD], g_EOlo[BSD];
__device__ __nv_bfloat16 g_Wthi[8 * Dq * Dq];   // transposed weights [n][k], hi
__device__ __nv_bfloat16 g_Wtlo[8 * Dq * Dq];   // lo

// ---------------- helpers (non-'a' ISA only) ----------------
__device__ __forceinline__ uint32_t smem_u32(const void* p) {
    uint32_t a;
    asm("{ .reg .u64 t; cvta.to.shared.u64 t, %1; cvt.u32.u64 %0, t; }" : "=r"(a) : "l"(p));
    return a;
}
__device__ __forceinline__ void ldsm_x4(uint32_t* r, uint32_t addr) {
    asm volatile("ldmatrix.sync.aligned.m8n8.x4.shared.b16 {%0,%1,%2,%3}, [%4];"
        : "=r"(r[0]), "=r"(r[1]), "=r"(r[2]), "=r"(r[3]) : "r"(addr));
}
__device__ __forceinline__ void ldsm_x2(uint32_t* r, uint32_t addr) {
    asm volatile("ldmatrix.sync.aligned.m8n8.x2.shared.b16 {%0,%1}, [%2];"
        : "=r"(r[0]), "=r"(r[1]) : "r"(addr));
}
__device__ __forceinline__ void ldsm_x2t(uint32_t* r, uint32_t addr) {
    asm volatile("ldmatrix.sync.aligned.m8n8.x2.trans.shared.b16 {%0,%1}, [%2];"
        : "=r"(r[0]), "=r"(r[1]) : "r"(addr));
}
__device__ __forceinline__ void mma16816(float* c, const uint32_t* a, const uint32_t* b) {
    asm volatile("mma.sync.aligned.m16n8k16.row.col.f32.bf16.bf16.f32 "
        "{%0,%1,%2,%3}, {%4,%5,%6,%7}, {%8,%9}, {%0,%1,%2,%3};"
        : "+f"(c[0]), "+f"(c[1]), "+f"(c[2]), "+f"(c[3])
        : "r"(a[0]), "r"(a[1]), "r"(a[2]), "r"(a[3]), "r"(b[0]), "r"(b[1]));
}
__device__ __forceinline__ void splitpk(float a, float b, uint32_t& hi, uint32_t& lo) {
    __nv_bfloat162 h = __floats2bfloat162_rn(a, b);
    float ra = a - __bfloat162float(h.x);
    float rb = b - __bfloat162float(h.y);
    __nv_bfloat162 l = __floats2bfloat162_rn(ra, rb);
    hi = *(uint32_t*)&h; lo = *(uint32_t*)&l;
}
#define CPA16(sa, gp) asm volatile("cp.async.cg.shared.global [%0], [%1], 16;" :: "r"(sa), "l"(gp))
#define CP_COMMIT()   asm volatile("cp.async.commit_group;")
#define CP_WAIT1()    asm volatile("cp.async.wait_group 1;" ::: "memory")

// ---------------- fused weight convert + transpose (all 8) ----------------
__global__ void __launch_bounds__(256) cvt_wt_all_kernel(
    const float* __restrict__ W0, const float* __restrict__ W1,
    const float* __restrict__ W2, const float* __restrict__ W3,
    const float* __restrict__ W4, const float* __restrict__ W5,
    const float* __restrict__ W6, const float* __restrict__ W7,
    __nv_bfloat16* __restrict__ hi, __nv_bfloat16* __restrict__ lo) {
    int w = blockIdx.y;
    const float* W = (w == 0) ? W0 : (w == 1) ? W1 : (w == 2) ? W2 : (w == 3) ? W3 :
                     (w == 4) ? W4 : (w == 5) ? W5 : (w == 6) ? W6 : W7;
    int idx = blockIdx.x * 256 + threadIdx.x;   // idx = n*512 + k
    int n = idx >> 9, k = idx & 511;
    float v = W[k * Dq + n];
    __nv_bfloat16 h = __float2bfloat16(v);
    size_t o = (size_t)w * Dq * Dq + idx;
    hi[o] = h;
    lo[o] = __float2bfloat16(v - __bfloat162float(h));
}

// ---------------- positional-embedding add (fp32 + split bf16 out) ----------------
__global__ void __launch_bounds__(256) add_pos_kernel(const float* __restrict__ x,
                                                      float* __restrict__ out,
                                                      __nv_bfloat16* __restrict__ ohi,
                                                      __nv_bfloat16* __restrict__ olo) {
    int idx = blockIdx.x * 256 + threadIdx.x;
    int d = idx & (Dq - 1);
    int s = (idx >> 9) & (Sq - 1);
    float freq  = expf((float)d * -0.0359778920794f);
    float angle = (float)s * freq;
    float pe = (d & 1) ? cosf(angle) : sinf(angle);
    float r = x[idx] + pe;
    out[idx] = r;
    __nv_bfloat16 h = __float2bfloat16(r);
    ohi[idx] = h;
    olo[idx] = __float2bfloat16(r - __bfloat162float(h));
}

// ---------------- fused LayerNorm + residual ----------------
__global__ void __launch_bounds__(256) ln_add_kernel(const float* __restrict__ x,
                                                     const float* __restrict__ gamma,
                                                     const float* __restrict__ beta,
                                                     const float* __restrict__ basep,
                                                     float scale,
                                                     float* __restrict__ out,
                                                     __nv_bfloat16* __restrict__ ohi,
                                                     __nv_bfloat16* __restrict__ olo) {
    __shared__ float red[256];
    int t = threadIdx.x;
    size_t off = (size_t)blockIdx.x * Dq;

    float v0 = x[off + t];
    float v1 = x[off + t + 256];

    red[t] = v0 + v1;
    __syncthreads();
    #pragma unroll
    for (int s2 = 128; s2 > 0; s2 >>= 1) {
        if (t < s2) red[t] += red[t + s2];
        __syncthreads();
    }
    float mu = red[0] * (1.0f / 512.0f);
    __syncthreads();

    float d0 = v0 - mu, d1 = v1 - mu;
    red[t] = d0 * d0 + d1 * d1;
    __syncthreads();
    #pragma unroll
    for (int s2 = 128; s2 > 0; s2 >>= 1) {
        if (t < s2) red[t] += red[t + s2];
        __syncthreads();
    }
    float var = red[0] * (1.0f / 512.0f);
    float rs  = rsqrtf(var + 1e-3f);

    float r0 = basep[off + t]       + scale * (d0 * rs * gamma[t]       + beta[t]);
    float r1 = basep[off + t + 256] + scale * (d1 * rs * gamma[t + 256] + beta[t + 256]);
    out[off + t]       = r0;
    out[off + t + 256] = r1;
    if (ohi) {
        __nv_bfloat16 h0 = __float2bfloat16(r0), h1 = __float2bfloat16(r1);
        ohi[off + t]       = h0;
        ohi[off + t + 256] = h1;
        olo[off + t]       = __float2bfloat16(r0 - __bfloat162float(h0));
        olo[off + t + 256] = __float2bfloat16(r1 - __bfloat162float(h1));
    }
}

// ---------------- GEMM core: K-chunk 32, cp.async double-buffered ----------------
// per-buffer layout (bytes): Ahi[128x40x2]=10240, Alo=10240, Bhi[64x40x2]=5120, Blo=5120
#define KAPAD 40
#define GA_HI 0
#define GA_LO 10240
#define GB_HI 20480
#define GB_LO 25600
#define GBUFSZ 30720
#define GEMM_SMEM (2 * GBUFSZ)   // 61440 -> 2 CTAs/SM

struct GemmFrag { float acc[2][4][4]; };

__device__ __forceinline__ void gemm_core(uint32_t sb,
                                          const __nv_bfloat16* __restrict__ Ahi,
                                          const __nv_bfloat16* __restrict__ Alo,
                                          const __nv_bfloat16* __restrict__ Bhi,
                                          const __nv_bfloat16* __restrict__ Blo,
                                          int m0, int n0, GemmFrag& F) {
    int tid = threadIdx.x;
    int wid = tid >> 5, lane = tid & 31;
    int wm = (wid & 3) * 32;
    int wn = (wid >> 2) * 32;

    #pragma unroll
    for (int i = 0; i < 2; i++)
        #pragma unroll
        for (int j = 0; j < 4; j++)
            #pragma unroll
            for (int q = 0; q < 4; q++) F.acc[i][j][q] = 0.0f;

    // load coordinates
    int rA = tid >> 1, cA = (tid & 1) * 16;   // 128 rows x 32 cols, 16 elems (32B? no, 16 elems=32B) -> two 16B? 16 bf16 = 32B
    int rB = tid >> 2, cB = (tid & 3) * 8;    // 64 rows x 32 cols, 8 elems = 16B

    // NOTE: 16 elems = 32 bytes -> two CPA16 per A row segment
    auto prefetch = [&](int kc, uint32_t bofs) {
        int kofs = kc * 32;
        uint32_t sAo = sb + bofs + (uint32_t)((rA * KAPAD + cA) * 2);
        const __nv_bfloat16* pAh = &Ahi[(size_t)(m0 + rA) * Dq + kofs + cA];
        const __nv_bfloat16* pAl = &Alo[(size_t)(m0 + rA) * Dq + kofs + cA];
        CPA16(sAo + GA_HI,      pAh);
        CPA16(sAo + GA_HI + 16, pAh + 8);
        CPA16(sAo + GA_LO,      pAl);
        CPA16(sAo + GA_LO + 16, pAl + 8);
        uint32_t sBo = sb + bofs + (uint32_t)((rB * KAPAD + cB) * 2);
        CPA16(sBo + GB_HI, &Bhi[(size_t)(n0 + rB) * Dq + kofs + cB]);
        CPA16(sBo + GB_LO, &Blo[(size_t)(n0 + rB) * Dq + kofs + cB]);
    };

    int la = lane & 15;
    int lacol = (lane >> 4) << 3;
    int lb = lane & 7;
    int lbcol = ((lane >> 3) & 1) << 3;

    prefetch(0, 0);
    CP_COMMIT();

    for (int kc = 0; kc < 16; kc++) {
        uint32_t cur = (kc & 1) ? GBUFSZ : 0;
        if (kc < 15) prefetch(kc + 1, (kc & 1) ? 0 : GBUFSZ);
        CP_COMMIT();
        CP_WAIT1();
        __syncthreads();

        #pragma unroll
        for (int ks = 0; ks < 2; ks++) {
            int kk = ks * 16;
            uint32_t ah[2][4], al[2][4];
            #pragma unroll
            for (int ma = 0; ma < 2; ma++) {
                int row = wm + ma * 16 + la;
                uint32_t off = cur + (uint32_t)((row * KAPAD + kk + lacol) * 2);
                ldsm_x4(ah[ma], sb + GA_HI + off);
                ldsm_x4(al[ma], sb + GA_LO + off);
            }
            uint32_t bh[4][2], bl[4][2];
            #pragma unroll
            for (int na = 0; na < 4; na++) {
                int rown = wn + na * 8 + lb;
                uint32_t off = cur + (uint32_t)((rown * KAPAD + kk + lbcol) * 2);
                ldsm_x2(bh[na], sb + GB_HI + off);
                ldsm_x2(bl[na], sb + GB_LO + off);
            }
            #pragma unroll
            for (int ma = 0; ma < 2; ma++)
                #pragma unroll
                for (int na = 0; na < 4; na++) {
                    mma16816(F.acc[ma][na], ah[ma], bh[na]);
                    mma16816(F.acc[ma][na], al[ma], bh[na]);
                    mma16816(F.acc[ma][na], ah[ma], bl[na]);
                }
        }
        __syncthreads();
    }
}

// ---- generic GEMM: fp32 out (+addend) and/or split-bf16 out ----
__global__ void __launch_bounds__(256, 2) gemm_mma_kernel(
    const __nv_bfloat16* __restrict__ Ahi, const __nv_bfloat16* __restrict__ Alo,
    const __nv_bfloat16* __restrict__ Bhi, const __nv_bfloat16* __restrict__ Blo,
    const float* __restrict__ addend, float* __restrict__ C,
    __nv_bfloat16* __restrict__ Chi, __nv_bfloat16* __restrict__ Clo) {
    extern __shared__ char smem[];
    uint32_t sb = smem_u32(smem);
    int m0 = blockIdx.y * 128, n0 = blockIdx.x * 64;
    GemmFrag F;
    gemm_core(sb, Ahi, Alo, Bhi, Blo, m0, n0, F);

    int wid = threadIdx.x >> 5, lane = threadIdx.x & 31;
    int wm = (wid & 3) * 32, wn = (wid >> 2) * 32;
    int g = lane >> 2, tq = lane & 3;
    #pragma unroll
    for (int ma = 0; ma < 2; ma++) {
        int row = m0 + wm + ma * 16 + g;
        #pragma unroll
        for (int na = 0; na < 4; na++) {
            int col = n0 + wn + na * 8 + tq * 2;
            size_t o0 = (size_t)row * Dq + col;
            size_t o1 = o0 + 8 * Dq;
            float2 r0 = make_float2(F.acc[ma][na][0], F.acc[ma][na][1]);
            float2 r1 = make_float2(F.acc[ma][na][2], F.acc[ma][na][3]);
            if (addend) {
                float2 a0 = *(const float2*)&addend[o0];
                float2 a1 = *(const float2*)&addend[o1];
                r0.x += a0.x; r0.y += a0.y;
                r1.x += a1.x; r1.y += a1.y;
            }
            if (C) {
                *(float2*)&C[o0] = r0;
                *(float2*)&C[o1] = r1;
            }
            if (Chi) {
                uint32_t h, l;
                splitpk(r0.x, r0.y, h, l);
                *(uint32_t*)&Chi[o0] = h; *(uint32_t*)&Clo[o0] = l;
                splitpk(r1.x, r1.y, h, l);
                *(uint32_t*)&Chi[o1] = h; *(uint32_t*)&Clo[o1] = l;
            }
        }
    }
}

// ---- fused QKV GEMM: 3 contiguous weights, bf16 hi/lo outputs ----
__global__ void __launch_bounds__(256, 2) gemm_qkv_kernel(
    const __nv_bfloat16* __restrict__ Ahi, const __nv_bfloat16* __restrict__ Alo,
    const __nv_bfloat16* __restrict__ Whi, const __nv_bfloat16* __restrict__ Wlo,
    __nv_bfloat16* __restrict__ Q0hi, __nv_bfloat16* __restrict__ Q0lo,
    __nv_bfloat16* __restrict__ K0hi, __nv_bfloat16* __restrict__ K0lo,
    __nv_bfloat16* __restrict__ V0hi, __nv_bfloat16* __restrict__ V0lo) {
    extern __shared__ char smem[];
    uint32_t sb = smem_u32(smem);
    int w = blockIdx.x >> 3;                 // 0=Q,1=K,2=V
    int n0 = (blockIdx.x & 7) * 64;
    int m0 = blockIdx.y * 128;
    const __nv_bfloat16* Bhi = Whi + (size_t)w * Dq * Dq;
    const __nv_bfloat16* Blo = Wlo + (size_t)w * Dq * Dq;
    __nv_bfloat16* Ohi = (w == 0) ? Q0hi : (w == 1) ? K0hi : V0hi;
    __nv_bfloat16* Olo = (w == 0) ? Q0lo : (w == 1) ? K0lo : V0lo;

    GemmFrag F;
    gemm_core(sb, Ahi, Alo, Bhi, Blo, m0, n0, F);

    int wid = threadIdx.x >> 5, lane = threadIdx.x & 31;
    int wm = (wid & 3) * 32, wn = (wid >> 2) * 32;
    int g = lane >> 2, tq = lane & 3;
    #pragma unroll
    for (int ma = 0; ma < 2; ma++) {
        int row = m0 + wm + ma * 16 + g;
        #pragma unroll
        for (int na = 0; na < 4; na++) {
            int col = n0 + wn + na * 8 + tq * 2;
            size_t o0 = (size_t)row * Dq + col;
            size_t o1 = o0 + 8 * Dq;
            uint32_t h, l;
            splitpk(F.acc[ma][na][0], F.acc[ma][na][1], h, l);
            *(uint32_t*)&Ohi[o0] = h; *(uint32_t*)&Olo[o0] = l;
            splitpk(F.acc[ma][na][2], F.acc[ma][na][3], h, l);
            *(uint32_t*)&Ohi[o1] = h; *(uint32_t*)&Olo[o1] = l;
        }
    }
}

// ---------------- mma.sync flash attention, 128q tiles + cp.async (R7, kept) ----------------
#define FP 72
#define FQHI 0
#define FQLO 18432
#define FKV  36864
#define KVH  0
#define KVL  9216
#define VVH  18432
#define VVL  27648
#define KVBUF 36864
#define FLASH_SMEM (FKV + 2 * KVBUF)   // 110592

__global__ void __launch_bounds__(256) flash_mma_kernel(
    const __nv_bfloat16* __restrict__ Qh, const __nv_bfloat16* __restrict__ Ql,
    const __nv_bfloat16* __restrict__ Kh, const __nv_bfloat16* __restrict__ Kl,
    const __nv_bfloat16* __restrict__ Vh, const __nv_bfloat16* __restrict__ Vl,
    float* __restrict__ O,
    __nv_bfloat16* __restrict__ Ohi, __nv_bfloat16* __restrict__ Olo) {
    extern __shared__ char smem[];
    uint32_t sb = smem_u32(smem);

    int tid = threadIdx.x, wid = tid >> 5, lane = tid & 31;
    int wm = wid * 16;
    int g = lane >> 2, tq = lane & 3;
    int qb = blockIdx.x, h = blockIdx.y, b = blockIdx.z;
    size_t baseQ  = ((size_t)b * Sq + (size_t)qb * 128) * Dq + h * DHq;
    size_t baseKV = (size_t)b * Sq * Dq + h * DHq;

    int rQ = tid >> 1, cQ = (tid & 1) * 32;
    int rK = tid >> 2, cK = (tid & 3) * 16;

    auto kvload = [&](int kb, uint32_t bofs) {
        size_t go = baseKV + (size_t)(kb * 64 + rK) * Dq + cK;
        uint32_t so = sb + FKV + bofs + (uint32_t)((rK * FP + cK) * 2);
        #pragma unroll
        for (int q = 0; q < 2; q++) {
            CPA16(so + KVH + q * 16, &Kh[go + q * 8]);
            CPA16(so + KVL + q * 16, &Kl[go + q * 8]);
            CPA16(so + VVH + q * 16, &Vh[go + q * 8]);
            CPA16(so + VVL + q * 16, &Vl[go + q * 8]);
        }
    };

    {
        size_t go = baseQ + (size_t)rQ * Dq + cQ;
        uint32_t so = sb + (uint32_t)((rQ * FP + cQ) * 2);
        #pragma unroll
        for (int q = 0; q < 4; q++) {
            CPA16(so + FQHI + q * 16, &Qh[go + q * 8]);
            CPA16(so + FQLO + q * 16, &Ql[go + q * 8]);
        }
        kvload(0, 0);
        CP_COMMIT();
    }

    float oacc[8][4];
    #pragma unroll
    for (int j = 0; j < 8; j++)
        #pragma unroll
        for (int q = 0; q < 4; q++) oacc[j][q] = 0.0f;
    float mr0 = -1e30f, mr1 = -1e30f, lr0 = 0.0f, lr1 = 0.0f;

    uint32_t aQ = (uint32_t)(((wm + (lane & 15)) * FP + ((lane >> 4) << 3)) * 2);
    uint32_t bK = (uint32_t)(((lane & 7) * FP + (((lane >> 3) & 1) << 3)) * 2);
    uint32_t bV = (uint32_t)(((lane & 15) * FP) * 2);

    for (int kb = 0; kb < 16; kb++) {
        uint32_t cur = FKV + ((kb & 1) ? KVBUF : 0);
        if (kb < 15) kvload(kb + 1, (kb & 1) ? 0 : KVBUF);
        CP_COMMIT();
        CP_WAIT1();
        __syncthreads();

        float sacc[8][4];
        #pragma unroll
        for (int j = 0; j < 8; j++)
            #pragma unroll
            for (int q = 0; q < 4; q++) sacc[j][q] = 0.0f;

        #pragma unroll
        for (int ks = 0; ks < 4; ks++) {
            uint32_t ah[4], al[4];
            ldsm_x4(ah, sb + FQHI + aQ + ks * 32);
            ldsm_x4(al, sb + FQLO + aQ + ks * 32);
            #pragma unroll
            for (int na = 0; na < 8; na++) {
                uint32_t bh[2], bl[2];
                uint32_t off = cur + bK + (uint32_t)(na * 8 * FP * 2) + ks * 32;
                ldsm_x2(bh, sb + KVH + off);
                ldsm_x2(bl, sb + KVL + off);
                mma16816(sacc[na], ah, bh);
                mma16816(sacc[na], al, bh);
                mma16816(sacc[na], ah, bl);
            }
        }

        float rmax0 = -1e30f, rmax1 = -1e30f;
        #pragma unroll
        for (int j = 0; j < 8; j++) {
            sacc[j][0] *= 0.125f; sacc[j][1] *= 0.125f;
            sacc[j][2] *= 0.125f; sacc[j][3] *= 0.125f;
            rmax0 = fmaxf(rmax0, fmaxf(sacc[j][0], sacc[j][1]));
            rmax1 = fmaxf(rmax1, fmaxf(sacc[j][2], sacc[j][3]));
        }
        rmax0 = fmaxf(rmax0, __shfl_xor_sync(0xffffffffu, rmax0, 1));
        rmax0 = fmaxf(rmax0, __shfl_xor_sync(0xffffffffu, rmax0, 2));
        rmax1 = fmaxf(rmax1, __shfl_xor_sync(0xffffffffu, rmax1, 1));
        rmax1 = fmaxf(rmax1, __shfl_xor_sync(0xffffffffu, rmax1, 2));
        float mn0 = fmaxf(mr0, rmax0), mn1 = fmaxf(mr1, rmax1);
        float al0 = __expf(mr0 - mn0), al1 = __expf(mr1 - mn1);
        float sum0 = 0.0f, sum1 = 0.0f;
        #pragma unroll
        for (int j = 0; j < 8; j++) {
            sacc[j][0] = __expf(sacc[j][0] - mn0);
            sacc[j][1] = __expf(sacc[j][1] - mn0);
            sacc[j][2] = __expf(sacc[j][2] - mn1);
            sacc[j][3] = __expf(sacc[j][3] - mn1);
            sum0 += sacc[j][0] + sacc[j][1];
            sum1 += sacc[j][2] + sacc[j][3];
        }
        sum0 += __shfl_xor_sync(0xffffffffu, sum0, 1);
        sum0 += __shfl_xor_sync(0xffffffffu, sum0, 2);
        sum1 += __shfl_xor_sync(0xffffffffu, sum1, 1);
        sum1 += __shfl_xor_sync(0xffffffffu, sum1, 2);
        lr0 = lr0 * al0 + sum0; mr0 = mn0;
        lr1 = lr1 * al1 + sum1; mr1 = mn1;

        #pragma unroll
        for (int j = 0; j < 8; j++) {
            oacc[j][0] *= al0; oacc[j][1] *= al0;
            oacc[j][2] *= al1; oacc[j][3] *= al1;
        }

        uint32_t ph[4][4], pl[4][4];
        #pragma unroll
        for (int k2 = 0; k2 < 4; k2++) {
            splitpk(sacc[2*k2][0],   sacc[2*k2][1],   ph[k2][0], pl[k2][0]);
            splitpk(sacc[2*k2][2],   sacc[2*k2][3],   ph[k2][1], pl[k2][1]);
            splitpk(sacc[2*k2+1][0], sacc[2*k2+1][1], ph[k2][2], pl[k2][2]);
            splitpk(sacc[2*k2+1][2], sacc[2*k2+1][3], ph[k2][3], pl[k2][3]);
        }

        #pragma unroll
        for (int k2 = 0; k2 < 4; k2++) {
            #pragma unroll
            for (int na = 0; na < 8; na++) {
                uint32_t bvh[2], bvl[2];
                uint32_t off = cur + bV + (uint32_t)((k2 * 16 * FP + na * 8) * 2);
                ldsm_x2t(bvh, sb + VVH + off);
                ldsm_x2t(bvl, sb + VVL + off);
                mma16816(oacc[na], ph[k2], bvh);
                mma16816(oacc[na], pl[k2], bvh);
                mma16816(oacc[na], ph[k2], bvl);
            }
        }
        __syncthreads();
    }

    float il0 = 1.0f / lr0, il1 = 1.0f / lr1;
    int row0 = wm + g, row1 = wm + g + 8;
    #pragma unroll
    for (int na = 0; na < 8; na++) {
        int col = na * 8 + tq * 2;
        float v00 = oacc[na][0] * il0, v01 = oacc[na][1] * il0;
        float v10 = oacc[na][2] * il1, v11 = oacc[na][3] * il1;
        size_t o0 = baseQ + (size_t)row0 * Dq + col;
        size_t o1 = baseQ + (size_t)row1 * Dq + col;
        if (O) {
            *(float2*)&O[o0] = make_float2(v00, v01);
            *(float2*)&O[o1] = make_float2(v10, v11);
        }
        if (Ohi) {
            uint32_t hh, ll;
            splitpk(v00, v01, hh, ll);
            *(uint32_t*)&Ohi[o0] = hh; *(uint32_t*)&Olo[o0] = ll;
            splitpk(v10, v11, hh, ll);
            *(uint32_t*)&Ohi[o1] = hh; *(uint32_t*)&Olo[o1] = ll;
        }
    }
}

// ---------------- launcher ----------------
extern "C" void kernel_launch(void* const* d_in, const int* in_sizes, int n_in,
                              void* d_out, int out_size) {
    const float* in0   = (const float*)d_in[0];
    const float* in1   = (const float*)d_in[1];
    const float* ge = (const float*)d_in[6];
    const float* be = (const float*)d_in[7];
    const float* gd = (const float*)d_in[12];
    const float* bd = (const float*)d_in[13];
    float* out = (float*)d_out;

    float *E, *DI, *Sb, *I, *EO;
    __nv_bfloat16 *Ahi, *Alo, *Qhi, *Qlo, *Khi, *Klo, *Vhi, *Vlo, *EOhi, *EOlo, *Whi, *Wlo;
    cudaGetSymbolAddress((void**)&E,    g_E);
    cudaGetSymbolAddress((void**)&DI,   g_DI);
    cudaGetSymbolAddress((void**)&Sb,   g_S);
    cudaGetSymbolAddress((void**)&I,    g_I);
    cudaGetSymbolAddress((void**)&EO,   g_EO);
    cudaGetSymbolAddress((void**)&Ahi,  g_Ahi);
    cudaGetSymbolAddress((void**)&Alo,  g_Alo);
    cudaGetSymbolAddress((void**)&Qhi,  g_Qhi);
    cudaGetSymbolAddress((void**)&Qlo,  g_Qlo);
    cudaGetSymbolAddress((void**)&Khi,  g_Khi);
    cudaGetSymbolAddress((void**)&Klo,  g_Klo);
    cudaGetSymbolAddress((void**)&Vhi,  g_Vhi);
    cudaGetSymbolAddress((void**)&Vlo,  g_Vlo);
    cudaGetSymbolAddress((void**)&EOhi, g_EOhi);
    cudaGetSymbolAddress((void**)&EOlo, g_EOlo);
    cudaGetSymbolAddress((void**)&Whi,  g_Wthi);
    cudaGetSymbolAddress((void**)&Wlo,  g_Wtlo);

    cudaFuncSetAttribute(gemm_mma_kernel,  cudaFuncAttributeMaxDynamicSharedMemorySize, GEMM_SMEM);
    cudaFuncSetAttribute(gemm_qkv_kernel,  cudaFuncAttributeMaxDynamicSharedMemorySize, GEMM_SMEM);
    cudaFuncSetAttribute(flash_mma_kernel, cudaFuncAttributeMaxDynamicSharedMemorySize, FLASH_SMEM);

    dim3 ggrid(Dq / 64, BSr / 128);        // (8, 64)
    dim3 qkvgrid(3 * Dq / 64, BSr / 128);  // (24, 64)
    dim3 fgrid(Sq / 128, Hq, Bq);          // (8, 8, 8)
    const int WSZ = Dq * Dq;

    dim3 wgrid(WSZ / 256, 8);
    cvt_wt_all_kernel<<<wgrid, 256>>>(
        (const float*)d_in[2], (const float*)d_in[3], (const float*)d_in[4],
        (const float*)d_in[5], (const float*)d_in[8], (const float*)d_in[9],
        (const float*)d_in[10], (const float*)d_in[11], Whi, Wlo);

    // ---- Encoder ----
    add_pos_kernel<<<BSD / 256, 256>>>(in0, E, Ahi, Alo);
    gemm_qkv_kernel<<<qkvgrid, 256, GEMM_SMEM>>>(Ahi, Alo, Whi, Wlo,
                                                 Qhi, Qlo, Khi, Klo, Vhi, Vlo);
    flash_mma_kernel<<<fgrid, 256, FLASH_SMEM>>>(Qhi, Qlo, Khi, Klo, Vhi, Vlo, Sb, nullptr, nullptr);
    ln_add_kernel<<<BSr, 256>>>(Sb, ge, be, E, 1.0f, I, Ahi, Alo);
    gemm_mma_kernel<<<ggrid, 256, GEMM_SMEM>>>(Ahi, Alo, Whi + 3 * WSZ, Wlo + 3 * WSZ, E, EO, EOhi, EOlo);

    // ---- Decoder ----
    add_pos_kernel<<<BSD / 256, 256>>>(in1, DI, Ahi, Alo);
    gemm_qkv_kernel<<<qkvgrid, 256, GEMM_SMEM>>>(Ahi, Alo, Whi + 4 * WSZ, Wlo + 4 * WSZ,
                                                 Qhi, Qlo, Khi, Klo, Vhi, Vlo);
    flash_mma_kernel<<<fgrid, 256, FLASH_SMEM>>>(Qhi, Qlo, Khi, Klo, Vhi, Vlo, Sb, nullptr, nullptr);
    ln_add_kernel<<<BSr, 256>>>(Sb, gd, bd, DI, 2.0f, I, nullptr, nullptr);
    flash_mma_kernel<<<fgrid, 256, FLASH_SMEM>>>(EOhi, EOlo, EOhi, EOlo, EOhi, EOlo,
                                                 nullptr, Ahi, Alo);   // eda -> bf16 only
    gemm_mma_kernel<<<ggrid, 256, GEMM_SMEM>>>(Ahi, Alo, Whi + 7 * WSZ, Wlo + 7 * WSZ, I, out, nullptr, nullptr);
}

// round 9
// speedup vs baseline: 1.0996x; 1.0996x over previous
#include <cuda_runtime.h>
#include <cuda_bf16.h>
#include <cstdint>
#include <math.h>

// Problem constants
#define Bq   8
#define Sq   1024
#define Dq   512
#define Hq   8
#define DHq  64
#define BSr  (Bq*Sq)        // 8192 rows
#define BSD  (Bq*Sq*Dq)     // 4194304 elements

// ---------------- device scratch (no allocations allowed) ----------------
__device__ float g_E [BSD];
__device__ float g_DI[BSD];
__device__ float g_S [BSD];
__device__ float g_I [BSD];
__device__ float g_EO[BSD];
__device__ __nv_bfloat16 g_Ahi[BSD], g_Alo[BSD];
__device__ __nv_bfloat16 g_Qhi[BSD], g_Qlo[BSD];
__device__ __nv_bfloat16 g_Khi[BSD], g_Klo[BSD];
__device__ __nv_bfloat16 g_Vhi[BSD], g_Vlo[BSD];
__device__ __nv_bfloat16 g_EOhi[BSD], g_EOlo[BSD];
__device__ __nv_bfloat16 g_Wthi[8 * Dq * Dq];   // transposed weights [n][k], hi
__device__ __nv_bfloat16 g_Wtlo[8 * Dq * Dq];   // lo

// ---------------- helpers (non-'a' ISA only) ----------------
__device__ __forceinline__ uint32_t smem_u32(const void* p) {
    uint32_t a;
    asm("{ .reg .u64 t; cvta.to.shared.u64 t, %1; cvt.u32.u64 %0, t; }" : "=r"(a) : "l"(p));
    return a;
}
__device__ __forceinline__ void ldsm_x4(uint32_t* r, uint32_t addr) {
    asm volatile("ldmatrix.sync.aligned.m8n8.x4.shared.b16 {%0,%1,%2,%3}, [%4];"
        : "=r"(r[0]), "=r"(r[1]), "=r"(r[2]), "=r"(r[3]) : "r"(addr));
}
__device__ __forceinline__ void ldsm_x2(uint32_t* r, uint32_t addr) {
    asm volatile("ldmatrix.sync.aligned.m8n8.x2.shared.b16 {%0,%1}, [%2];"
        : "=r"(r[0]), "=r"(r[1]) : "r"(addr));
}
__device__ __forceinline__ void ldsm_x2t(uint32_t* r, uint32_t addr) {
    asm volatile("ldmatrix.sync.aligned.m8n8.x2.trans.shared.b16 {%0,%1}, [%2];"
        : "=r"(r[0]), "=r"(r[1]) : "r"(addr));
}
__device__ __forceinline__ void mma16816(float* c, const uint32_t* a, const uint32_t* b) {
    asm volatile("mma.sync.aligned.m16n8k16.row.col.f32.bf16.bf16.f32 "
        "{%0,%1,%2,%3}, {%4,%5,%6,%7}, {%8,%9}, {%0,%1,%2,%3};"
        : "+f"(c[0]), "+f"(c[1]), "+f"(c[2]), "+f"(c[3])
        : "r"(a[0]), "r"(a[1]), "r"(a[2]), "r"(a[3]), "r"(b[0]), "r"(b[1]));
}
__device__ __forceinline__ void splitpk(float a, float b, uint32_t& hi, uint32_t& lo) {
    __nv_bfloat162 h = __floats2bfloat162_rn(a, b);
    float ra = a - __bfloat162float(h.x);
    float rb = b - __bfloat162float(h.y);
    __nv_bfloat162 l = __floats2bfloat162_rn(ra, rb);
    hi = *(uint32_t*)&h; lo = *(uint32_t*)&l;
}
#define CPA16(sa, gp) asm volatile("cp.async.cg.shared.global [%0], [%1], 16;" :: "r"(sa), "l"(gp))
#define CP_COMMIT()   asm volatile("cp.async.commit_group;")
#define CP_WAIT0()    asm volatile("cp.async.wait_group 0;" ::: "memory")

// ---------------- fused weight convert + transpose (all 8) ----------------
__global__ void __launch_bounds__(256) cvt_wt_all_kernel(
    const float* __restrict__ W0, const float* __restrict__ W1,
    const float* __restrict__ W2, const float* __restrict__ W3,
    const float* __restrict__ W4, const float* __restrict__ W5,
    const float* __restrict__ W6, const float* __restrict__ W7,
    __nv_bfloat16* __restrict__ hi, __nv_bfloat16* __restrict__ lo) {
    int w = blockIdx.y;
    const float* W = (w == 0) ? W0 : (w == 1) ? W1 : (w == 2) ? W2 : (w == 3) ? W3 :
                     (w == 4) ? W4 : (w == 5) ? W5 : (w == 6) ? W6 : W7;
    int idx = blockIdx.x * 256 + threadIdx.x;   // idx = n*512 + k
    int n = idx >> 9, k = idx & 511;
    float v = W[k * Dq + n];
    __nv_bfloat16 h = __float2bfloat16(v);
    size_t o = (size_t)w * Dq * Dq + idx;
    hi[o] = h;
    lo[o] = __float2bfloat16(v - __bfloat162float(h));
}

// ---------------- positional-embedding add (fp32 + split bf16 out) ----------------
__global__ void __launch_bounds__(256) add_pos_kernel(const float* __restrict__ x,
                                                      float* __restrict__ out,
                                                      __nv_bfloat16* __restrict__ ohi,
                                                      __nv_bfloat16* __restrict__ olo) {
    int idx = blockIdx.x * 256 + threadIdx.x;
    int d = idx & (Dq - 1);
    int s = (idx >> 9) & (Sq - 1);
    float freq  = expf((float)d * -0.0359778920794f);
    float angle = (float)s * freq;
    float pe = (d & 1) ? cosf(angle) : sinf(angle);
    float r = x[idx] + pe;
    out[idx] = r;
    __nv_bfloat16 h = __float2bfloat16(r);
    ohi[idx] = h;
    olo[idx] = __float2bfloat16(r - __bfloat162float(h));
}

// ---------------- fused LayerNorm + residual ----------------
__global__ void __launch_bounds__(256) ln_add_kernel(const float* __restrict__ x,
                                                     const float* __restrict__ gamma,
                                                     const float* __restrict__ beta,
                                                     const float* __restrict__ basep,
                                                     float scale,
                                                     float* __restrict__ out,
                                                     __nv_bfloat16* __restrict__ ohi,
                                                     __nv_bfloat16* __restrict__ olo) {
    __shared__ float red[256];
    int t = threadIdx.x;
    size_t off = (size_t)blockIdx.x * Dq;

    float v0 = x[off + t];
    float v1 = x[off + t + 256];

    red[t] = v0 + v1;
    __syncthreads();
    #pragma unroll
    for (int s2 = 128; s2 > 0; s2 >>= 1) {
        if (t < s2) red[t] += red[t + s2];
        __syncthreads();
    }
    float mu = red[0] * (1.0f / 512.0f);
    __syncthreads();

    float d0 = v0 - mu, d1 = v1 - mu;
    red[t] = d0 * d0 + d1 * d1;
    __syncthreads();
    #pragma unroll
    for (int s2 = 128; s2 > 0; s2 >>= 1) {
        if (t < s2) red[t] += red[t + s2];
        __syncthreads();
    }
    float var = red[0] * (1.0f / 512.0f);
    float rs  = rsqrtf(var + 1e-3f);

    float r0 = basep[off + t]       + scale * (d0 * rs * gamma[t]       + beta[t]);
    float r1 = basep[off + t + 256] + scale * (d1 * rs * gamma[t + 256] + beta[t + 256]);
    out[off + t]       = r0;
    out[off + t + 256] = r1;
    if (ohi) {
        __nv_bfloat16 h0 = __float2bfloat16(r0), h1 = __float2bfloat16(r1);
        ohi[off + t]       = h0;
        ohi[off + t + 256] = h1;
        olo[off + t]       = __float2bfloat16(r0 - __bfloat162float(h0));
        olo[off + t + 256] = __float2bfloat16(r1 - __bfloat162float(h1));
    }
}

// ---------------- GEMM core (R5 single-buffer K64, proven fast) ----------------
#define APAD 72
#define SA_HI 0
#define SA_LO 18432
#define SB_HI 36864
#define SB_LO 46080
#define GEMM_SMEM 55296

struct GemmFrag { float acc[2][4][4]; };

__device__ __forceinline__ void gemm_core(uint32_t sb, char* smem,
                                          const __nv_bfloat16* __restrict__ Ahi,
                                          const __nv_bfloat16* __restrict__ Alo,
                                          const __nv_bfloat16* __restrict__ Bhi,
                                          const __nv_bfloat16* __restrict__ Blo,
                                          int m0, int n0, GemmFrag& F) {
    __nv_bfloat16* sAhi = (__nv_bfloat16*)(smem + SA_HI);
    __nv_bfloat16* sAlo = (__nv_bfloat16*)(smem + SA_LO);
    __nv_bfloat16* sBhi = (__nv_bfloat16*)(smem + SB_HI);
    __nv_bfloat16* sBlo = (__nv_bfloat16*)(smem + SB_LO);

    int tid = threadIdx.x;
    int wid = tid >> 5, lane = tid & 31;
    int wm = (wid & 3) * 32;
    int wn = (wid >> 2) * 32;

    #pragma unroll
    for (int i = 0; i < 2; i++)
        #pragma unroll
        for (int j = 0; j < 4; j++)
            #pragma unroll
            for (int q = 0; q < 4; q++) F.acc[i][j][q] = 0.0f;

    int la = lane & 15;
    int lacol = (lane >> 4) << 3;
    int lb = lane & 7;
    int lbcol = ((lane >> 3) & 1) << 3;

    for (int kc = 0; kc < 8; kc++) {
        int kofs = kc * 64;
        #pragma unroll
        for (int p = 0; p < 4; p++) {
            int e = tid + p * 256;
            int r = e >> 3, c8 = (e & 7) * 8;
            size_t go = (size_t)(m0 + r) * Dq + kofs + c8;
            *(uint4*)&sAhi[r * APAD + c8] = *(const uint4*)&Ahi[go];
            *(uint4*)&sAlo[r * APAD + c8] = *(const uint4*)&Alo[go];
        }
        #pragma unroll
        for (int p = 0; p < 2; p++) {
            int e = tid + p * 256;
            int r = e >> 3, c8 = (e & 7) * 8;
            size_t go = (size_t)(n0 + r) * Dq + kofs + c8;
            *(uint4*)&sBhi[r * APAD + c8] = *(const uint4*)&Bhi[go];
            *(uint4*)&sBlo[r * APAD + c8] = *(const uint4*)&Blo[go];
        }
        __syncthreads();

        #pragma unroll
        for (int ks = 0; ks < 4; ks++) {
            int kk = ks * 16;
            uint32_t ah[2][4], al[2][4];
            #pragma unroll
            for (int ma = 0; ma < 2; ma++) {
                int row = wm + ma * 16 + la;
                uint32_t off = (uint32_t)((row * APAD + kk + lacol) * 2);
                ldsm_x4(ah[ma], sb + SA_HI + off);
                ldsm_x4(al[ma], sb + SA_LO + off);
            }
            uint32_t bh[4][2], bl[4][2];
            #pragma unroll
            for (int na = 0; na < 4; na++) {
                int rown = wn + na * 8 + lb;
                uint32_t off = (uint32_t)((rown * APAD + kk + lbcol) * 2);
                ldsm_x2(bh[na], sb + SB_HI + off);
                ldsm_x2(bl[na], sb + SB_LO + off);
            }
            #pragma unroll
            for (int ma = 0; ma < 2; ma++)
                #pragma unroll
                for (int na = 0; na < 4; na++) {
                    mma16816(F.acc[ma][na], ah[ma], bh[na]);
                    mma16816(F.acc[ma][na], al[ma], bh[na]);
                    mma16816(F.acc[ma][na], ah[ma], bl[na]);
                }
        }
        __syncthreads();
    }
}

// ---- generic GEMM: fp32 out (+addend) and/or split-bf16 out ----
__global__ void __launch_bounds__(256) gemm_mma_kernel(
    const __nv_bfloat16* __restrict__ Ahi, const __nv_bfloat16* __restrict__ Alo,
    const __nv_bfloat16* __restrict__ Bhi, const __nv_bfloat16* __restrict__ Blo,
    const float* __restrict__ addend, float* __restrict__ C,
    __nv_bfloat16* __restrict__ Chi, __nv_bfloat16* __restrict__ Clo) {
    extern __shared__ char smem[];
    uint32_t sb = smem_u32(smem);
    int m0 = blockIdx.y * 128, n0 = blockIdx.x * 64;
    GemmFrag F;
    gemm_core(sb, smem, Ahi, Alo, Bhi, Blo, m0, n0, F);

    int wid = threadIdx.x >> 5, lane = threadIdx.x & 31;
    int wm = (wid & 3) * 32, wn = (wid >> 2) * 32;
    int g = lane >> 2, tq = lane & 3;
    #pragma unroll
    for (int ma = 0; ma < 2; ma++) {
        int row = m0 + wm + ma * 16 + g;
        #pragma unroll
        for (int na = 0; na < 4; na++) {
            int col = n0 + wn + na * 8 + tq * 2;
            size_t o0 = (size_t)row * Dq + col;
            size_t o1 = o0 + 8 * Dq;
            float2 r0 = make_float2(F.acc[ma][na][0], F.acc[ma][na][1]);
            float2 r1 = make_float2(F.acc[ma][na][2], F.acc[ma][na][3]);
            if (addend) {
                float2 a0 = *(const float2*)&addend[o0];
                float2 a1 = *(const float2*)&addend[o1];
                r0.x += a0.x; r0.y += a0.y;
                r1.x += a1.x; r1.y += a1.y;
            }
            if (C) {
                *(float2*)&C[o0] = r0;
                *(float2*)&C[o1] = r1;
            }
            if (Chi) {
                uint32_t h, l;
                splitpk(r0.x, r0.y, h, l);
                *(uint32_t*)&Chi[o0] = h; *(uint32_t*)&Clo[o0] = l;
                splitpk(r1.x, r1.y, h, l);
                *(uint32_t*)&Chi[o1] = h; *(uint32_t*)&Clo[o1] = l;
            }
        }
    }
}

// ---- fused QKV GEMM: 3 contiguous weights, bf16 hi/lo outputs ----
__global__ void __launch_bounds__(256) gemm_qkv_kernel(
    const __nv_bfloat16* __restrict__ Ahi, const __nv_bfloat16* __restrict__ Alo,
    const __nv_bfloat16* __restrict__ Whi, const __nv_bfloat16* __restrict__ Wlo,
    __nv_bfloat16* __restrict__ Q0hi, __nv_bfloat16* __restrict__ Q0lo,
    __nv_bfloat16* __restrict__ K0hi, __nv_bfloat16* __restrict__ K0lo,
    __nv_bfloat16* __restrict__ V0hi, __nv_bfloat16* __restrict__ V0lo) {
    extern __shared__ char smem[];
    uint32_t sb = smem_u32(smem);
    int w = blockIdx.x >> 3;                 // 0=Q,1=K,2=V
    int n0 = (blockIdx.x & 7) * 64;
    int m0 = blockIdx.y * 128;
    const __nv_bfloat16* Bhi = Whi + (size_t)w * Dq * Dq;
    const __nv_bfloat16* Blo = Wlo + (size_t)w * Dq * Dq;
    __nv_bfloat16* Ohi = (w == 0) ? Q0hi : (w == 1) ? K0hi : V0hi;
    __nv_bfloat16* Olo = (w == 0) ? Q0lo : (w == 1) ? K0lo : V0lo;

    GemmFrag F;
    gemm_core(sb, smem, Ahi, Alo, Bhi, Blo, m0, n0, F);

    int wid = threadIdx.x >> 5, lane = threadIdx.x & 31;
    int wm = (wid & 3) * 32, wn = (wid >> 2) * 32;
    int g = lane >> 2, tq = lane & 3;
    #pragma unroll
    for (int ma = 0; ma < 2; ma++) {
        int row = m0 + wm + ma * 16 + g;
        #pragma unroll
        for (int na = 0; na < 4; na++) {
            int col = n0 + wn + na * 8 + tq * 2;
            size_t o0 = (size_t)row * Dq + col;
            size_t o1 = o0 + 8 * Dq;
            uint32_t h, l;
            splitpk(F.acc[ma][na][0], F.acc[ma][na][1], h, l);
            *(uint32_t*)&Ohi[o0] = h; *(uint32_t*)&Olo[o0] = l;
            splitpk(F.acc[ma][na][2], F.acc[ma][na][3], h, l);
            *(uint32_t*)&Ohi[o1] = h; *(uint32_t*)&Olo[o1] = l;
        }
    }
}

// ---------------- flash attention: 128q tiles, SINGLE-buffer KV (2 CTAs/SM) ----------------
#define FP 72
#define FQHI 0
#define FQLO 18432
#define FKV  36864
#define KVH  0
#define KVL  9216
#define VVH  18432
#define VVL  27648
#define FLASH_SMEM (FKV + 36864)   // 73728 -> 2 CTAs/SM

__global__ void __launch_bounds__(256) flash_mma_kernel(
    const __nv_bfloat16* __restrict__ Qh, const __nv_bfloat16* __restrict__ Ql,
    const __nv_bfloat16* __restrict__ Kh, const __nv_bfloat16* __restrict__ Kl,
    const __nv_bfloat16* __restrict__ Vh, const __nv_bfloat16* __restrict__ Vl,
    float* __restrict__ O,
    __nv_bfloat16* __restrict__ Ohi, __nv_bfloat16* __restrict__ Olo) {
    extern __shared__ char smem[];
    uint32_t sb = smem_u32(smem);

    int tid = threadIdx.x, wid = tid >> 5, lane = tid & 31;
    int wm = wid * 16;
    int g = lane >> 2, tq = lane & 3;
    int qb = blockIdx.x, h = blockIdx.y, b = blockIdx.z;
    size_t baseQ  = ((size_t)b * Sq + (size_t)qb * 128) * Dq + h * DHq;
    size_t baseKV = (size_t)b * Sq * Dq + h * DHq;

    int rQ = tid >> 1, cQ = (tid & 1) * 32;
    int rK = tid >> 2, cK = (tid & 3) * 16;

    auto kvload = [&](int kb) {
        size_t go = baseKV + (size_t)(kb * 64 + rK) * Dq + cK;
        uint32_t so = sb + FKV + (uint32_t)((rK * FP + cK) * 2);
        #pragma unroll
        for (int q = 0; q < 2; q++) {
            CPA16(so + KVH + q * 16, &Kh[go + q * 8]);
            CPA16(so + KVL + q * 16, &Kl[go + q * 8]);
            CPA16(so + VVH + q * 16, &Vh[go + q * 8]);
            CPA16(so + VVL + q * 16, &Vl[go + q * 8]);
        }
    };

    {   // Q + KV tile 0
        size_t go = baseQ + (size_t)rQ * Dq + cQ;
        uint32_t so = sb + (uint32_t)((rQ * FP + cQ) * 2);
        #pragma unroll
        for (int q = 0; q < 4; q++) {
            CPA16(so + FQHI + q * 16, &Qh[go + q * 8]);
            CPA16(so + FQLO + q * 16, &Ql[go + q * 8]);
        }
        kvload(0);
        CP_COMMIT();
        CP_WAIT0();
        __syncthreads();
    }

    float oacc[8][4];
    #pragma unroll
    for (int j = 0; j < 8; j++)
        #pragma unroll
        for (int q = 0; q < 4; q++) oacc[j][q] = 0.0f;
    float mr0 = -1e30f, mr1 = -1e30f, lr0 = 0.0f, lr1 = 0.0f;

    uint32_t aQ = (uint32_t)(((wm + (lane & 15)) * FP + ((lane >> 4) << 3)) * 2);
    uint32_t bK = (uint32_t)(((lane & 7) * FP + (((lane >> 3) & 1) << 3)) * 2);
    uint32_t bV = (uint32_t)(((lane & 15) * FP) * 2);

    for (int kb = 0; kb < 16; kb++) {
        // S = Q @ K^T (3-pass split)
        float sacc[8][4];
        #pragma unroll
        for (int j = 0; j < 8; j++)
            #pragma unroll
            for (int q = 0; q < 4; q++) sacc[j][q] = 0.0f;

        #pragma unroll
        for (int ks = 0; ks < 4; ks++) {
            uint32_t ah[4], al[4];
            ldsm_x4(ah, sb + FQHI + aQ + ks * 32);
            ldsm_x4(al, sb + FQLO + aQ + ks * 32);
            #pragma unroll
            for (int na = 0; na < 8; na++) {
                uint32_t bh[2], bl[2];
                uint32_t off = FKV + bK + (uint32_t)(na * 8 * FP * 2) + ks * 32;
                ldsm_x2(bh, sb + KVH + off);
                ldsm_x2(bl, sb + KVL + off);
                mma16816(sacc[na], ah, bh);
                mma16816(sacc[na], al, bh);
                mma16816(sacc[na], ah, bl);
            }
        }

        // Register softmax
        float rmax0 = -1e30f, rmax1 = -1e30f;
        #pragma unroll
        for (int j = 0; j < 8; j++) {
            sacc[j][0] *= 0.125f; sacc[j][1] *= 0.125f;
            sacc[j][2] *= 0.125f; sacc[j][3] *= 0.125f;
            rmax0 = fmaxf(rmax0, fmaxf(sacc[j][0], sacc[j][1]));
            rmax1 = fmaxf(rmax1, fmaxf(sacc[j][2], sacc[j][3]));
        }
        rmax0 = fmaxf(rmax0, __shfl_xor_sync(0xffffffffu, rmax0, 1));
        rmax0 = fmaxf(rmax0, __shfl_xor_sync(0xffffffffu, rmax0, 2));
        rmax1 = fmaxf(rmax1, __shfl_xor_sync(0xffffffffu, rmax1, 1));
        rmax1 = fmaxf(rmax1, __shfl_xor_sync(0xffffffffu, rmax1, 2));
        float mn0 = fmaxf(mr0, rmax0), mn1 = fmaxf(mr1, rmax1);
        float al0 = __expf(mr0 - mn0), al1 = __expf(mr1 - mn1);
        float sum0 = 0.0f, sum1 = 0.0f;
        #pragma unroll
        for (int j = 0; j < 8; j++) {
            sacc[j][0] = __expf(sacc[j][0] - mn0);
            sacc[j][1] = __expf(sacc[j][1] - mn0);
            sacc[j][2] = __expf(sacc[j][2] - mn1);
            sacc[j][3] = __expf(sacc[j][3] - mn1);
            sum0 += sacc[j][0] + sacc[j][1];
            sum1 += sacc[j][2] + sacc[j][3];
        }
        sum0 += __shfl_xor_sync(0xffffffffu, sum0, 1);
        sum0 += __shfl_xor_sync(0xffffffffu, sum0, 2);
        sum1 += __shfl_xor_sync(0xffffffffu, sum1, 1);
        sum1 += __shfl_xor_sync(0xffffffffu, sum1, 2);
        lr0 = lr0 * al0 + sum0; mr0 = mn0;
        lr1 = lr1 * al1 + sum1; mr1 = mn1;

        #pragma unroll
        for (int j = 0; j < 8; j++) {
            oacc[j][0] *= al0; oacc[j][1] *= al0;
            oacc[j][2] *= al1; oacc[j][3] *= al1;
        }

        // Re-pack P into A fragments, split hi/lo
        uint32_t ph[4][4], pl[4][4];
        #pragma unroll
        for (int k2 = 0; k2 < 4; k2++) {
            splitpk(sacc[2*k2][0],   sacc[2*k2][1],   ph[k2][0], pl[k2][0]);
            splitpk(sacc[2*k2][2],   sacc[2*k2][3],   ph[k2][1], pl[k2][1]);
            splitpk(sacc[2*k2+1][0], sacc[2*k2+1][1], ph[k2][2], pl[k2][2]);
            splitpk(sacc[2*k2+1][2], sacc[2*k2+1][3], ph[k2][3], pl[k2][3]);
        }

        // O += P @ V (3-pass split; V via ldmatrix.trans)
        #pragma unroll
        for (int k2 = 0; k2 < 4; k2++) {
            #pragma unroll
            for (int na = 0; na < 8; na++) {
                uint32_t bvh[2], bvl[2];
                uint32_t off = FKV + bV + (uint32_t)((k2 * 16 * FP + na * 8) * 2);
                ldsm_x2t(bvh, sb + VVH + off);
                ldsm_x2t(bvl, sb + VVL + off);
                mma16816(oacc[na], ph[k2], bvh);
                mma16816(oacc[na], pl[k2], bvh);
                mma16816(oacc[na], ph[k2], bvl);
            }
        }

        // refill single KV buffer for next tile
        __syncthreads();
        if (kb < 15) {
            kvload(kb + 1);
            CP_COMMIT();
            CP_WAIT0();
            __syncthreads();
        }
    }

    float il0 = 1.0f / lr0, il1 = 1.0f / lr1;
    int row0 = wm + g, row1 = wm + g + 8;
    #pragma unroll
    for (int na = 0; na < 8; na++) {
        int col = na * 8 + tq * 2;
        float v00 = oacc[na][0] * il0, v01 = oacc[na][1] * il0;
        float v10 = oacc[na][2] * il1, v11 = oacc[na][3] * il1;
        size_t o0 = baseQ + (size_t)row0 * Dq + col;
        size_t o1 = baseQ + (size_t)row1 * Dq + col;
        if (O) {
            *(float2*)&O[o0] = make_float2(v00, v01);
            *(float2*)&O[o1] = make_float2(v10, v11);
        }
        if (Ohi) {
            uint32_t hh, ll;
            splitpk(v00, v01, hh, ll);
            *(uint32_t*)&Ohi[o0] = hh; *(uint32_t*)&Olo[o0] = ll;
            splitpk(v10, v11, hh, ll);
            *(uint32_t*)&Ohi[o1] = hh; *(uint32_t*)&Olo[o1] = ll;
        }
    }
}

// ---------------- launcher ----------------
extern "C" void kernel_launch(void* const* d_in, const int* in_sizes, int n_in,
                              void* d_out, int out_size) {
    const float* in0   = (const float*)d_in[0];
    const float* in1   = (const float*)d_in[1];
    const float* ge = (const float*)d_in[6];
    const float* be = (const float*)d_in[7];
    const float* gd = (const float*)d_in[12];
    const float* bd = (const float*)d_in[13];
    float* out = (float*)d_out;

    float *E, *DI, *Sb, *I, *EO;
    __nv_bfloat16 *Ahi, *Alo, *Qhi, *Qlo, *Khi, *Klo, *Vhi, *Vlo, *EOhi, *EOlo, *Whi, *Wlo;
    cudaGetSymbolAddress((void**)&E,    g_E);
    cudaGetSymbolAddress((void**)&DI,   g_DI);
    cudaGetSymbolAddress((void**)&Sb,   g_S);
    cudaGetSymbolAddress((void**)&I,    g_I);
    cudaGetSymbolAddress((void**)&EO,   g_EO);
    cudaGetSymbolAddress((void**)&Ahi,  g_Ahi);
    cudaGetSymbolAddress((void**)&Alo,  g_Alo);
    cudaGetSymbolAddress((void**)&Qhi,  g_Qhi);
    cudaGetSymbolAddress((void**)&Qlo,  g_Qlo);
    cudaGetSymbolAddress((void**)&Khi,  g_Khi);
    cudaGetSymbolAddress((void**)&Klo,  g_Klo);
    cudaGetSymbolAddress((void**)&Vhi,  g_Vhi);
    cudaGetSymbolAddress((void**)&Vlo,  g_Vlo);
    cudaGetSymbolAddress((void**)&EOhi, g_EOhi);
    cudaGetSymbolAddress((void**)&EOlo, g_EOlo);
    cudaGetSymbolAddress((void**)&Whi,  g_Wthi);
    cudaGetSymbolAddress((void**)&Wlo,  g_Wtlo);

    cudaFuncSetAttribute(gemm_mma_kernel,  cudaFuncAttributeMaxDynamicSharedMemorySize, GEMM_SMEM);
    cudaFuncSetAttribute(gemm_qkv_kernel,  cudaFuncAttributeMaxDynamicSharedMemorySize, GEMM_SMEM);
    cudaFuncSetAttribute(flash_mma_kernel, cudaFuncAttributeMaxDynamicSharedMemorySize, FLASH_SMEM);

    dim3 ggrid(Dq / 64, BSr / 128);        // (8, 64)
    dim3 qkvgrid(3 * Dq / 64, BSr / 128);  // (24, 64)
    dim3 fgrid(Sq / 128, Hq, Bq);          // (8, 8, 8)
    const int WSZ = Dq * Dq;

    dim3 wgrid(WSZ / 256, 8);
    cvt_wt_all_kernel<<<wgrid, 256>>>(
        (const float*)d_in[2], (const float*)d_in[3], (const float*)d_in[4],
        (const float*)d_in[5], (const float*)d_in[8], (const float*)d_in[9],
        (const float*)d_in[10], (const float*)d_in[11], Whi, Wlo);

    // ---- Encoder ----
    add_pos_kernel<<<BSD / 256, 256>>>(in0, E, Ahi, Alo);
    gemm_qkv_kernel<<<qkvgrid, 256, GEMM_SMEM>>>(Ahi, Alo, Whi, Wlo,
                                                 Qhi, Qlo, Khi, Klo, Vhi, Vlo);
    flash_mma_kernel<<<fgrid, 256, FLASH_SMEM>>>(Qhi, Qlo, Khi, Klo, Vhi, Vlo, Sb, nullptr, nullptr);
    ln_add_kernel<<<BSr, 256>>>(Sb, ge, be, E, 1.0f, I, Ahi, Alo);
    gemm_mma_kernel<<<ggrid, 256, GEMM_SMEM>>>(Ahi, Alo, Whi + 3 * WSZ, Wlo + 3 * WSZ, E, EO, EOhi, EOlo);

    // ---- Decoder ----
    add_pos_kernel<<<BSD / 256, 256>>>(in1, DI, Ahi, Alo);
    gemm_qkv_kernel<<<qkvgrid, 256, GEMM_SMEM>>>(Ahi, Alo, Whi + 4 * WSZ, Wlo + 4 * WSZ,
                                                 Qhi, Qlo, Khi, Klo, Vhi, Vlo);
    flash_mma_kernel<<<fgrid, 256, FLASH_SMEM>>>(Qhi, Qlo, Khi, Klo, Vhi, Vlo, Sb, nullptr, nullptr);
    ln_add_kernel<<<BSr, 256>>>(Sb, gd, bd, DI, 2.0f, I, nullptr, nullptr);
    flash_mma_kernel<<<fgrid, 256, FLASH_SMEM>>>(EOhi, EOlo, EOhi, EOlo, EOhi, EOlo,
                                                 nullptr, Ahi, Alo);   // eda -> bf16 only
    gemm_mma_kernel<<<ggrid, 256, GEMM_SMEM>>>(Ahi, Alo, Whi + 7 * WSZ, Wlo + 7 * WSZ, I, out, nullptr, nullptr);
}

// round 10
// speedup vs baseline: 1.3114x; 1.1926x over previous
#include <cuda_runtime.h>
#include <cuda_bf16.h>
#include <cuda_fp16.h>
#include <cstdint>
#include <math.h>

// Problem constants
#define Bq   8
#define Sq   1024
#define Dq   512
#define Hq   8
#define DHq  64
#define BSr  (Bq*Sq)        // 8192 rows
#define BSD  (Bq*Sq*Dq)     // 4194304 elements

// ---------------- device scratch (no allocations allowed) ----------------
__device__ float g_E [BSD];
__device__ float g_DI[BSD];
__device__ float g_S [BSD];
__device__ float g_I [BSD];
__device__ float g_EO[BSD];
__device__ __nv_bfloat16 g_Ahi[BSD], g_Alo[BSD];
__device__ __nv_bfloat16 g_Qhi[BSD], g_Qlo[BSD];
__device__ __nv_bfloat16 g_Khi[BSD], g_Klo[BSD];
__device__ __half        g_V16[BSD];
__device__ __nv_bfloat16 g_EOhi[BSD], g_EOlo[BSD];
__device__ __half        g_EO16[BSD];
__device__ __nv_bfloat16 g_Wthi[8 * Dq * Dq];   // transposed weights [n][k], hi
__device__ __nv_bfloat16 g_Wtlo[8 * Dq * Dq];   // lo

// ---------------- helpers (non-'a' ISA only) ----------------
__device__ __forceinline__ uint32_t smem_u32(const void* p) {
    uint32_t a;
    asm("{ .reg .u64 t; cvta.to.shared.u64 t, %1; cvt.u32.u64 %0, t; }" : "=r"(a) : "l"(p));
    return a;
}
__device__ __forceinline__ void ldsm_x4(uint32_t* r, uint32_t addr) {
    asm volatile("ldmatrix.sync.aligned.m8n8.x4.shared.b16 {%0,%1,%2,%3}, [%4];"
        : "=r"(r[0]), "=r"(r[1]), "=r"(r[2]), "=r"(r[3]) : "r"(addr));
}
__device__ __forceinline__ void ldsm_x2(uint32_t* r, uint32_t addr) {
    asm volatile("ldmatrix.sync.aligned.m8n8.x2.shared.b16 {%0,%1}, [%2];"
        : "=r"(r[0]), "=r"(r[1]) : "r"(addr));
}
__device__ __forceinline__ void ldsm_x2t(uint32_t* r, uint32_t addr) {
    asm volatile("ldmatrix.sync.aligned.m8n8.x2.trans.shared.b16 {%0,%1}, [%2];"
        : "=r"(r[0]), "=r"(r[1]) : "r"(addr));
}
__device__ __forceinline__ void mma16816(float* c, const uint32_t* a, const uint32_t* b) {
    asm volatile("mma.sync.aligned.m16n8k16.row.col.f32.bf16.bf16.f32 "
        "{%0,%1,%2,%3}, {%4,%5,%6,%7}, {%8,%9}, {%0,%1,%2,%3};"
        : "+f"(c[0]), "+f"(c[1]), "+f"(c[2]), "+f"(c[3])
        : "r"(a[0]), "r"(a[1]), "r"(a[2]), "r"(a[3]), "r"(b[0]), "r"(b[1]));
}
__device__ __forceinline__ void mma16816h(float* c, const uint32_t* a, const uint32_t* b) {
    asm volatile("mma.sync.aligned.m16n8k16.row.col.f32.f16.f16.f32 "
        "{%0,%1,%2,%3}, {%4,%5,%6,%7}, {%8,%9}, {%0,%1,%2,%3};"
        : "+f"(c[0]), "+f"(c[1]), "+f"(c[2]), "+f"(c[3])
        : "r"(a[0]), "r"(a[1]), "r"(a[2]), "r"(a[3]), "r"(b[0]), "r"(b[1]));
}
__device__ __forceinline__ void splitpk(float a, float b, uint32_t& hi, uint32_t& lo) {
    __nv_bfloat162 h = __floats2bfloat162_rn(a, b);
    float ra = a - __bfloat162float(h.x);
    float rb = b - __bfloat162float(h.y);
    __nv_bfloat162 l = __floats2bfloat162_rn(ra, rb);
    hi = *(uint32_t*)&h; lo = *(uint32_t*)&l;
}
__device__ __forceinline__ uint32_t pkh2(float a, float b) {
    __half2 h = __floats2half2_rn(a, b);
    return *(uint32_t*)&h;
}
#define CPA16(sa, gp) asm volatile("cp.async.cg.shared.global [%0], [%1], 16;" :: "r"(sa), "l"(gp))
#define CP_COMMIT()   asm volatile("cp.async.commit_group;")
#define CP_WAIT0()    asm volatile("cp.async.wait_group 0;" ::: "memory")

// ---------------- fused weight convert + transpose (all 8) ----------------
__global__ void __launch_bounds__(256) cvt_wt_all_kernel(
    const float* __restrict__ W0, const float* __restrict__ W1,
    const float* __restrict__ W2, const float* __restrict__ W3,
    const float* __restrict__ W4, const float* __restrict__ W5,
    const float* __restrict__ W6, const float* __restrict__ W7,
    __nv_bfloat16* __restrict__ hi, __nv_bfloat16* __restrict__ lo) {
    int w = blockIdx.y;
    const float* W = (w == 0) ? W0 : (w == 1) ? W1 : (w == 2) ? W2 : (w == 3) ? W3 :
                     (w == 4) ? W4 : (w == 5) ? W5 : (w == 6) ? W6 : W7;
    int idx = blockIdx.x * 256 + threadIdx.x;   // idx = n*512 + k
    int n = idx >> 9, k = idx & 511;
    float v = W[k * Dq + n];
    __nv_bfloat16 h = __float2bfloat16(v);
    size_t o = (size_t)w * Dq * Dq + idx;
    hi[o] = h;
    lo[o] = __float2bfloat16(v - __bfloat162float(h));
}

// ---------------- positional-embedding add (fp32 + split bf16 out) ----------------
__global__ void __launch_bounds__(256) add_pos_kernel(const float* __restrict__ x,
                                                      float* __restrict__ out,
                                                      __nv_bfloat16* __restrict__ ohi,
                                                      __nv_bfloat16* __restrict__ olo) {
    int idx = blockIdx.x * 256 + threadIdx.x;
    int d = idx & (Dq - 1);
    int s = (idx >> 9) & (Sq - 1);
    float freq  = expf((float)d * -0.0359778920794f);
    float angle = (float)s * freq;
    float pe = (d & 1) ? cosf(angle) : sinf(angle);
    float r = x[idx] + pe;
    out[idx] = r;
    __nv_bfloat16 h = __float2bfloat16(r);
    ohi[idx] = h;
    olo[idx] = __float2bfloat16(r - __bfloat162float(h));
}

// ---------------- fused LayerNorm + residual ----------------
__global__ void __launch_bounds__(256) ln_add_kernel(const float* __restrict__ x,
                                                     const float* __restrict__ gamma,
                                                     const float* __restrict__ beta,
                                                     const float* __restrict__ basep,
                                                     float scale,
                                                     float* __restrict__ out,
                                                     __nv_bfloat16* __restrict__ ohi,
                                                     __nv_bfloat16* __restrict__ olo) {
    __shared__ float red[256];
    int t = threadIdx.x;
    size_t off = (size_t)blockIdx.x * Dq;

    float v0 = x[off + t];
    float v1 = x[off + t + 256];

    red[t] = v0 + v1;
    __syncthreads();
    #pragma unroll
    for (int s2 = 128; s2 > 0; s2 >>= 1) {
        if (t < s2) red[t] += red[t + s2];
        __syncthreads();
    }
    float mu = red[0] * (1.0f / 512.0f);
    __syncthreads();

    float d0 = v0 - mu, d1 = v1 - mu;
    red[t] = d0 * d0 + d1 * d1;
    __syncthreads();
    #pragma unroll
    for (int s2 = 128; s2 > 0; s2 >>= 1) {
        if (t < s2) red[t] += red[t + s2];
        __syncthreads();
    }
    float var = red[0] * (1.0f / 512.0f);
    float rs  = rsqrtf(var + 1e-3f);

    float r0 = basep[off + t]       + scale * (d0 * rs * gamma[t]       + beta[t]);
    float r1 = basep[off + t + 256] + scale * (d1 * rs * gamma[t + 256] + beta[t + 256]);
    out[off + t]       = r0;
    out[off + t + 256] = r1;
    if (ohi) {
        __nv_bfloat16 h0 = __float2bfloat16(r0), h1 = __float2bfloat16(r1);
        ohi[off + t]       = h0;
        ohi[off + t + 256] = h1;
        olo[off + t]       = __float2bfloat16(r0 - __bfloat162float(h0));
        olo[off + t + 256] = __float2bfloat16(r1 - __bfloat162float(h1));
    }
}

// ---------------- GEMM core (single-buffer K64, proven fast) ----------------
#define APAD 72
#define SA_HI 0
#define SA_LO 18432
#define SB_HI 36864
#define SB_LO 46080
#define GEMM_SMEM 55296

struct GemmFrag { float acc[2][4][4]; };

__device__ __forceinline__ void gemm_core(uint32_t sb, char* smem,
                                          const __nv_bfloat16* __restrict__ Ahi,
                                          const __nv_bfloat16* __restrict__ Alo,
                                          const __nv_bfloat16* __restrict__ Bhi,
                                          const __nv_bfloat16* __restrict__ Blo,
                                          int m0, int n0, GemmFrag& F) {
    __nv_bfloat16* sAhi = (__nv_bfloat16*)(smem + SA_HI);
    __nv_bfloat16* sAlo = (__nv_bfloat16*)(smem + SA_LO);
    __nv_bfloat16* sBhi = (__nv_bfloat16*)(smem + SB_HI);
    __nv_bfloat16* sBlo = (__nv_bfloat16*)(smem + SB_LO);

    int tid = threadIdx.x;
    int wid = tid >> 5, lane = tid & 31;
    int wm = (wid & 3) * 32;
    int wn = (wid >> 2) * 32;

    #pragma unroll
    for (int i = 0; i < 2; i++)
        #pragma unroll
        for (int j = 0; j < 4; j++)
            #pragma unroll
            for (int q = 0; q < 4; q++) F.acc[i][j][q] = 0.0f;

    int la = lane & 15;
    int lacol = (lane >> 4) << 3;
    int lb = lane & 7;
    int lbcol = ((lane >> 3) & 1) << 3;

    for (int kc = 0; kc < 8; kc++) {
        int kofs = kc * 64;
        #pragma unroll
        for (int p = 0; p < 4; p++) {
            int e = tid + p * 256;
            int r = e >> 3, c8 = (e & 7) * 8;
            size_t go = (size_t)(m0 + r) * Dq + kofs + c8;
            *(uint4*)&sAhi[r * APAD + c8] = *(const uint4*)&Ahi[go];
            *(uint4*)&sAlo[r * APAD + c8] = *(const uint4*)&Alo[go];
        }
        #pragma unroll
        for (int p = 0; p < 2; p++) {
            int e = tid + p * 256;
            int r = e >> 3, c8 = (e & 7) * 8;
            size_t go = (size_t)(n0 + r) * Dq + kofs + c8;
            *(uint4*)&sBhi[r * APAD + c8] = *(const uint4*)&Bhi[go];
            *(uint4*)&sBlo[r * APAD + c8] = *(const uint4*)&Blo[go];
        }
        __syncthreads();

        #pragma unroll
        for (int ks = 0; ks < 4; ks++) {
            int kk = ks * 16;
            uint32_t ah[2][4], al[2][4];
            #pragma unroll
            for (int ma = 0; ma < 2; ma++) {
                int row = wm + ma * 16 + la;
                uint32_t off = (uint32_t)((row * APAD + kk + lacol) * 2);
                ldsm_x4(ah[ma], sb + SA_HI + off);
                ldsm_x4(al[ma], sb + SA_LO + off);
            }
            uint32_t bh[4][2], bl[4][2];
            #pragma unroll
            for (int na = 0; na < 4; na++) {
                int rown = wn + na * 8 + lb;
                uint32_t off = (uint32_t)((rown * APAD + kk + lbcol) * 2);
                ldsm_x2(bh[na], sb + SB_HI + off);
                ldsm_x2(bl[na], sb + SB_LO + off);
            }
            #pragma unroll
            for (int ma = 0; ma < 2; ma++)
                #pragma unroll
                for (int na = 0; na < 4; na++) {
                    mma16816(F.acc[ma][na], ah[ma], bh[na]);
                    mma16816(F.acc[ma][na], al[ma], bh[na]);
                    mma16816(F.acc[ma][na], ah[ma], bl[na]);
                }
        }
        __syncthreads();
    }
}

// ---- generic GEMM: fp32 out (+addend) and/or split-bf16 out and/or fp16 out ----
__global__ void __launch_bounds__(256) gemm_mma_kernel(
    const __nv_bfloat16* __restrict__ Ahi, const __nv_bfloat16* __restrict__ Alo,
    const __nv_bfloat16* __restrict__ Bhi, const __nv_bfloat16* __restrict__ Blo,
    const float* __restrict__ addend, float* __restrict__ C,
    __nv_bfloat16* __restrict__ Chi, __nv_bfloat16* __restrict__ Clo,
    __half* __restrict__ C16) {
    extern __shared__ char smem[];
    uint32_t sb = smem_u32(smem);
    int m0 = blockIdx.y * 128, n0 = blockIdx.x * 64;
    GemmFrag F;
    gemm_core(sb, smem, Ahi, Alo, Bhi, Blo, m0, n0, F);

    int wid = threadIdx.x >> 5, lane = threadIdx.x & 31;
    int wm = (wid & 3) * 32, wn = (wid >> 2) * 32;
    int g = lane >> 2, tq = lane & 3;
    #pragma unroll
    for (int ma = 0; ma < 2; ma++) {
        int row = m0 + wm + ma * 16 + g;
        #pragma unroll
        for (int na = 0; na < 4; na++) {
            int col = n0 + wn + na * 8 + tq * 2;
            size_t o0 = (size_t)row * Dq + col;
            size_t o1 = o0 + 8 * Dq;
            float2 r0 = make_float2(F.acc[ma][na][0], F.acc[ma][na][1]);
            float2 r1 = make_float2(F.acc[ma][na][2], F.acc[ma][na][3]);
            if (addend) {
                float2 a0 = *(const float2*)&addend[o0];
                float2 a1 = *(const float2*)&addend[o1];
                r0.x += a0.x; r0.y += a0.y;
                r1.x += a1.x; r1.y += a1.y;
            }
            if (C) {
                *(float2*)&C[o0] = r0;
                *(float2*)&C[o1] = r1;
            }
            if (Chi) {
                uint32_t h, l;
                splitpk(r0.x, r0.y, h, l);
                *(uint32_t*)&Chi[o0] = h; *(uint32_t*)&Clo[o0] = l;
                splitpk(r1.x, r1.y, h, l);
                *(uint32_t*)&Chi[o1] = h; *(uint32_t*)&Clo[o1] = l;
            }
            if (C16) {
                *(uint32_t*)&C16[o0] = pkh2(r0.x, r0.y);
                *(uint32_t*)&C16[o1] = pkh2(r1.x, r1.y);
            }
        }
    }
}

// ---- fused QKV GEMM: Q,K -> split bf16; V -> fp16 ----
__global__ void __launch_bounds__(256) gemm_qkv_kernel(
    const __nv_bfloat16* __restrict__ Ahi, const __nv_bfloat16* __restrict__ Alo,
    const __nv_bfloat16* __restrict__ Whi, const __nv_bfloat16* __restrict__ Wlo,
    __nv_bfloat16* __restrict__ Q0hi, __nv_bfloat16* __restrict__ Q0lo,
    __nv_bfloat16* __restrict__ K0hi, __nv_bfloat16* __restrict__ K0lo,
    __half* __restrict__ V16) {
    extern __shared__ char smem[];
    uint32_t sb = smem_u32(smem);
    int w = blockIdx.x >> 3;                 // 0=Q,1=K,2=V
    int n0 = (blockIdx.x & 7) * 64;
    int m0 = blockIdx.y * 128;
    const __nv_bfloat16* Bhi = Whi + (size_t)w * Dq * Dq;
    const __nv_bfloat16* Blo = Wlo + (size_t)w * Dq * Dq;

    GemmFrag F;
    gemm_core(sb, smem, Ahi, Alo, Bhi, Blo, m0, n0, F);

    int wid = threadIdx.x >> 5, lane = threadIdx.x & 31;
    int wm = (wid & 3) * 32, wn = (wid >> 2) * 32;
    int g = lane >> 2, tq = lane & 3;
    __nv_bfloat16* Ohi = (w == 0) ? Q0hi : K0hi;
    __nv_bfloat16* Olo = (w == 0) ? Q0lo : K0lo;
    #pragma unroll
    for (int ma = 0; ma < 2; ma++) {
        int row = m0 + wm + ma * 16 + g;
        #pragma unroll
        for (int na = 0; na < 4; na++) {
            int col = n0 + wn + na * 8 + tq * 2;
            size_t o0 = (size_t)row * Dq + col;
            size_t o1 = o0 + 8 * Dq;
            if (w < 2) {
                uint32_t h, l;
                splitpk(F.acc[ma][na][0], F.acc[ma][na][1], h, l);
                *(uint32_t*)&Ohi[o0] = h; *(uint32_t*)&Olo[o0] = l;
                splitpk(F.acc[ma][na][2], F.acc[ma][na][3], h, l);
                *(uint32_t*)&Ohi[o1] = h; *(uint32_t*)&Olo[o1] = l;
            } else {
                *(uint32_t*)&V16[o0] = pkh2(F.acc[ma][na][0], F.acc[ma][na][1]);
                *(uint32_t*)&V16[o1] = pkh2(F.acc[ma][na][2], F.acc[ma][na][3]);
            }
        }
    }
}

// ---------------- flash attention: 128q tiles, QK split-bf16, PV fp16 single-pass ----------------
#define FP 72
#define FQHI 0
#define FQLO 18432
#define FKV  36864
#define KVH  0
#define KVL  9216
#define VV16 18432
#define FLASH_SMEM (FKV + 27648)   // 64512

#define LOG2E_DIV_H 0.18033688f    // log2(e)/8

__global__ void __launch_bounds__(256) flash_mma_kernel(
    const __nv_bfloat16* __restrict__ Qh, const __nv_bfloat16* __restrict__ Ql,
    const __nv_bfloat16* __restrict__ Kh, const __nv_bfloat16* __restrict__ Kl,
    const __half* __restrict__ V16,
    float* __restrict__ O,
    __nv_bfloat16* __restrict__ Ohi, __nv_bfloat16* __restrict__ Olo) {
    extern __shared__ char smem[];
    uint32_t sb = smem_u32(smem);

    int tid = threadIdx.x, wid = tid >> 5, lane = tid & 31;
    int wm = wid * 16;
    int g = lane >> 2, tq = lane & 3;
    int qb = blockIdx.x, h = blockIdx.y, b = blockIdx.z;
    size_t baseQ  = ((size_t)b * Sq + (size_t)qb * 128) * Dq + h * DHq;
    size_t baseKV = (size_t)b * Sq * Dq + h * DHq;

    int rQ = tid >> 1, cQ = (tid & 1) * 32;
    int rK = tid >> 2, cK = (tid & 3) * 16;

    auto kvload = [&](int kb) {
        size_t go = baseKV + (size_t)(kb * 64 + rK) * Dq + cK;
        uint32_t so = sb + FKV + (uint32_t)((rK * FP + cK) * 2);
        #pragma unroll
        for (int q = 0; q < 2; q++) {
            CPA16(so + KVH + q * 16, &Kh[go + q * 8]);
            CPA16(so + KVL + q * 16, &Kl[go + q * 8]);
            CPA16(so + VV16 + q * 16, &V16[go + q * 8]);
        }
    };

    {   // Q + KV tile 0
        size_t go = baseQ + (size_t)rQ * Dq + cQ;
        uint32_t so = sb + (uint32_t)((rQ * FP + cQ) * 2);
        #pragma unroll
        for (int q = 0; q < 4; q++) {
            CPA16(so + FQHI + q * 16, &Qh[go + q * 8]);
            CPA16(so + FQLO + q * 16, &Ql[go + q * 8]);
        }
        kvload(0);
        CP_COMMIT();
        CP_WAIT0();
        __syncthreads();
    }

    float oacc[8][4];
    #pragma unroll
    for (int j = 0; j < 8; j++)
        #pragma unroll
        for (int q = 0; q < 4; q++) oacc[j][q] = 0.0f;
    float mr0 = -1e30f, mr1 = -1e30f, lr0 = 0.0f, lr1 = 0.0f;

    uint32_t aQ = (uint32_t)(((wm + (lane & 15)) * FP + ((lane >> 4) << 3)) * 2);
    uint32_t bK = (uint32_t)(((lane & 7) * FP + (((lane >> 3) & 1) << 3)) * 2);
    uint32_t bV = (uint32_t)(((lane & 15) * FP) * 2);

    for (int kb = 0; kb < 16; kb++) {
        // S = Q @ K^T (3-pass split bf16)
        float sacc[8][4];
        #pragma unroll
        for (int j = 0; j < 8; j++)
            #pragma unroll
            for (int q = 0; q < 4; q++) sacc[j][q] = 0.0f;

        #pragma unroll
        for (int ks = 0; ks < 4; ks++) {
            uint32_t ah[4], al[4];
            ldsm_x4(ah, sb + FQHI + aQ + ks * 32);
            ldsm_x4(al, sb + FQLO + aQ + ks * 32);
            #pragma unroll
            for (int na = 0; na < 8; na++) {
                uint32_t bh[2], bl[2];
                uint32_t off = FKV + bK + (uint32_t)(na * 8 * FP * 2) + ks * 32;
                ldsm_x2(bh, sb + KVH + off);
                ldsm_x2(bl, sb + KVL + off);
                mma16816(sacc[na], ah, bh);
                mma16816(sacc[na], al, bh);
                mma16816(sacc[na], ah, bl);
            }
        }

        // Register softmax in exp2 domain (scores pre-scaled by log2e/H)
        float rmax0 = -1e30f, rmax1 = -1e30f;
        #pragma unroll
        for (int j = 0; j < 8; j++) {
            sacc[j][0] *= LOG2E_DIV_H; sacc[j][1] *= LOG2E_DIV_H;
            sacc[j][2] *= LOG2E_DIV_H; sacc[j][3] *= LOG2E_DIV_H;
            rmax0 = fmaxf(rmax0, fmaxf(sacc[j][0], sacc[j][1]));
            rmax1 = fmaxf(rmax1, fmaxf(sacc[j][2], sacc[j][3]));
        }
        rmax0 = fmaxf(rmax0, __shfl_xor_sync(0xffffffffu, rmax0, 1));
        rmax0 = fmaxf(rmax0, __shfl_xor_sync(0xffffffffu, rmax0, 2));
        rmax1 = fmaxf(rmax1, __shfl_xor_sync(0xffffffffu, rmax1, 1));
        rmax1 = fmaxf(rmax1, __shfl_xor_sync(0xffffffffu, rmax1, 2));
        float mn0 = fmaxf(mr0, rmax0), mn1 = fmaxf(mr1, rmax1);
        float al0 = exp2f(mr0 - mn0), al1 = exp2f(mr1 - mn1);
        float sum0 = 0.0f, sum1 = 0.0f;
        #pragma unroll
        for (int j = 0; j < 8; j++) {
            sacc[j][0] = exp2f(sacc[j][0] - mn0);
            sacc[j][1] = exp2f(sacc[j][1] - mn0);
            sacc[j][2] = exp2f(sacc[j][2] - mn1);
            sacc[j][3] = exp2f(sacc[j][3] - mn1);
            sum0 += sacc[j][0] + sacc[j][1];
            sum1 += sacc[j][2] + sacc[j][3];
        }
        sum0 += __shfl_xor_sync(0xffffffffu, sum0, 1);
        sum0 += __shfl_xor_sync(0xffffffffu, sum0, 2);
        sum1 += __shfl_xor_sync(0xffffffffu, sum1, 1);
        sum1 += __shfl_xor_sync(0xffffffffu, sum1, 2);
        lr0 = lr0 * al0 + sum0; mr0 = mn0;
        lr1 = lr1 * al1 + sum1; mr1 = mn1;

        #pragma unroll
        for (int j = 0; j < 8; j++) {
            oacc[j][0] *= al0; oacc[j][1] *= al0;
            oacc[j][2] *= al1; oacc[j][3] *= al1;
        }

        // Re-pack P into fp16 A fragments (single pass)
        uint32_t ph[4][4];
        #pragma unroll
        for (int k2 = 0; k2 < 4; k2++) {
            ph[k2][0] = pkh2(sacc[2*k2][0],   sacc[2*k2][1]);
            ph[k2][1] = pkh2(sacc[2*k2][2],   sacc[2*k2][3]);
            ph[k2][2] = pkh2(sacc[2*k2+1][0], sacc[2*k2+1][1]);
            ph[k2][3] = pkh2(sacc[2*k2+1][2], sacc[2*k2+1][3]);
        }

        // O += P @ V (single-pass fp16; V via ldmatrix.trans)
        #pragma unroll
        for (int k2 = 0; k2 < 4; k2++) {
            #pragma unroll
            for (int na = 0; na < 8; na++) {
                uint32_t bv[2];
                uint32_t off = FKV + bV + (uint32_t)((k2 * 16 * FP + na * 8) * 2);
                ldsm_x2t(bv, sb + VV16 + off);
                mma16816h(oacc[na], ph[k2], bv);
            }
        }

        // refill single KV buffer for next tile
        __syncthreads();
        if (kb < 15) {
            kvload(kb + 1);
            CP_COMMIT();
            CP_WAIT0();
            __syncthreads();
        }
    }

    float il0 = 1.0f / lr0, il1 = 1.0f / lr1;
    int row0 = wm + g, row1 = wm + g + 8;
    #pragma unroll
    for (int na = 0; na < 8; na++) {
        int col = na * 8 + tq * 2;
        float v00 = oacc[na][0] * il0, v01 = oacc[na][1] * il0;
        float v10 = oacc[na][2] * il1, v11 = oacc[na][3] * il1;
        size_t o0 = baseQ + (size_t)row0 * Dq + col;
        size_t o1 = baseQ + (size_t)row1 * Dq + col;
        if (O) {
            *(float2*)&O[o0] = make_float2(v00, v01);
            *(float2*)&O[o1] = make_float2(v10, v11);
        }
        if (Ohi) {
            uint32_t hh, ll;
            splitpk(v00, v01, hh, ll);
            *(uint32_t*)&Ohi[o0] = hh; *(uint32_t*)&Olo[o0] = ll;
            splitpk(v10, v11, hh, ll);
            *(uint32_t*)&Ohi[o1] = hh; *(uint32_t*)&Olo[o1] = ll;
        }
    }
}

// ---------------- launcher ----------------
extern "C" void kernel_launch(void* const* d_in, const int* in_sizes, int n_in,
                              void* d_out, int out_size) {
    const float* in0   = (const float*)d_in[0];
    const float* in1   = (const float*)d_in[1];
    const float* ge = (const float*)d_in[6];
    const float* be = (const float*)d_in[7];
    const float* gd = (const float*)d_in[12];
    const float* bd = (const float*)d_in[13];
    float* out = (float*)d_out;

    float *E, *DI, *Sb, *I, *EO;
    __nv_bfloat16 *Ahi, *Alo, *Qhi, *Qlo, *Khi, *Klo, *EOhi, *EOlo, *Whi, *Wlo;
    __half *V16, *EO16;
    cudaGetSymbolAddress((void**)&E,    g_E);
    cudaGetSymbolAddress((void**)&DI,   g_DI);
    cudaGetSymbolAddress((void**)&Sb,   g_S);
    cudaGetSymbolAddress((void**)&I,    g_I);
    cudaGetSymbolAddress((void**)&EO,   g_EO);
    cudaGetSymbolAddress((void**)&Ahi,  g_Ahi);
    cudaGetSymbolAddress((void**)&Alo,  g_Alo);
    cudaGetSymbolAddress((void**)&Qhi,  g_Qhi);
    cudaGetSymbolAddress((void**)&Qlo,  g_Qlo);
    cudaGetSymbolAddress((void**)&Khi,  g_Khi);
    cudaGetSymbolAddress((void**)&Klo,  g_Klo);
    cudaGetSymbolAddress((void**)&V16,  g_V16);
    cudaGetSymbolAddress((void**)&EOhi, g_EOhi);
    cudaGetSymbolAddress((void**)&EOlo, g_EOlo);
    cudaGetSymbolAddress((void**)&EO16, g_EO16);
    cudaGetSymbolAddress((void**)&Whi,  g_Wthi);
    cudaGetSymbolAddress((void**)&Wlo,  g_Wtlo);

    cudaFuncSetAttribute(gemm_mma_kernel,  cudaFuncAttributeMaxDynamicSharedMemorySize, GEMM_SMEM);
    cudaFuncSetAttribute(gemm_qkv_kernel,  cudaFuncAttributeMaxDynamicSharedMemorySize, GEMM_SMEM);
    cudaFuncSetAttribute(flash_mma_kernel, cudaFuncAttributeMaxDynamicSharedMemorySize, FLASH_SMEM);

    dim3 ggrid(Dq / 64, BSr / 128);        // (8, 64)
    dim3 qkvgrid(3 * Dq / 64, BSr / 128);  // (24, 64)
    dim3 fgrid(Sq / 128, Hq, Bq);          // (8, 8, 8)
    const int WSZ = Dq * Dq;

    dim3 wgrid(WSZ / 256, 8);
    cvt_wt_all_kernel<<<wgrid, 256>>>(
        (const float*)d_in[2], (const float*)d_in[3], (const float*)d_in[4],
        (const float*)d_in[5], (const float*)d_in[8], (const float*)d_in[9],
        (const float*)d_in[10], (const float*)d_in[11], Whi, Wlo);

    // ---- Encoder ----
    add_pos_kernel<<<BSD / 256, 256>>>(in0, E, Ahi, Alo);
    gemm_qkv_kernel<<<qkvgrid, 256, GEMM_SMEM>>>(Ahi, Alo, Whi, Wlo,
                                                 Qhi, Qlo, Khi, Klo, V16);
    flash_mma_kernel<<<fgrid, 256, FLASH_SMEM>>>(Qhi, Qlo, Khi, Klo, V16, Sb, nullptr, nullptr);
    ln_add_kernel<<<BSr, 256>>>(Sb, ge, be, E, 1.0f, I, Ahi, Alo);
    gemm_mma_kernel<<<ggrid, 256, GEMM_SMEM>>>(Ahi, Alo, Whi + 3 * WSZ, Wlo + 3 * WSZ,
                                               E, EO, EOhi, EOlo, EO16);

    // ---- Decoder ----
    add_pos_kernel<<<BSD / 256, 256>>>(in1, DI, Ahi, Alo);
    gemm_qkv_kernel<<<qkvgrid, 256, GEMM_SMEM>>>(Ahi, Alo, Whi + 4 * WSZ, Wlo + 4 * WSZ,
                                                 Qhi, Qlo, Khi, Klo, V16);
    flash_mma_kernel<<<fgrid, 256, FLASH_SMEM>>>(Qhi, Qlo, Khi, Klo, V16, Sb, nullptr, nullptr);
    ln_add_kernel<<<BSr, 256>>>(Sb, gd, bd, DI, 2.0f, I, nullptr, nullptr);
    flash_mma_kernel<<<fgrid, 256, FLASH_SMEM>>>(EOhi, EOlo, EOhi, EOlo, EO16,
                                                 nullptr, Ahi, Alo);   // eda -> bf16 only
    gemm_mma_kernel<<<ggrid, 256, GEMM_SMEM>>>(Ahi, Alo, Whi + 7 * WSZ, Wlo + 7 * WSZ,
                                               I, out, nullptr, nullptr, nullptr);
}

// round 11
// speedup vs baseline: 1.8596x; 1.4181x over previous
#include <cuda_runtime.h>
#include <cuda_bf16.h>
#include <cuda_fp16.h>
#include <cstdint>
#include <math.h>

// Problem constants
#define Bq   8
#define Sq   1024
#define Dq   512
#define Hq   8
#define DHq  64
#define BSr  (Bq*Sq)        // 8192 rows
#define BSD  (Bq*Sq*Dq)     // 4194304 elements

// ---------------- device scratch (no allocations allowed) ----------------
__device__ float g_E [BSD];
__device__ float g_DI[BSD];
__device__ float g_S [BSD];
__device__ float g_I [BSD];
__device__ __half g_A16[BSD];
__device__ __half g_Q16[BSD];
__device__ __half g_K16[BSD];
__device__ __half g_V16[BSD];
__device__ __half g_EO16[BSD];
__device__ __half g_Wh16[8 * Dq * Dq];   // transposed weights [n][k], fp16 hi
__device__ __half g_Wl16[8 * Dq * Dq];   // fp16 lo (residual)

// ---------------- helpers (non-'a' ISA only) ----------------
__device__ __forceinline__ uint32_t smem_u32(const void* p) {
    uint32_t a;
    asm("{ .reg .u64 t; cvta.to.shared.u64 t, %1; cvt.u32.u64 %0, t; }" : "=r"(a) : "l"(p));
    return a;
}
__device__ __forceinline__ void ldsm_x4(uint32_t* r, uint32_t addr) {
    asm volatile("ldmatrix.sync.aligned.m8n8.x4.shared.b16 {%0,%1,%2,%3}, [%4];"
        : "=r"(r[0]), "=r"(r[1]), "=r"(r[2]), "=r"(r[3]) : "r"(addr));
}
__device__ __forceinline__ void ldsm_x2(uint32_t* r, uint32_t addr) {
    asm volatile("ldmatrix.sync.aligned.m8n8.x2.shared.b16 {%0,%1}, [%2];"
        : "=r"(r[0]), "=r"(r[1]) : "r"(addr));
}
__device__ __forceinline__ void ldsm_x2t(uint32_t* r, uint32_t addr) {
    asm volatile("ldmatrix.sync.aligned.m8n8.x2.trans.shared.b16 {%0,%1}, [%2];"
        : "=r"(r[0]), "=r"(r[1]) : "r"(addr));
}
__device__ __forceinline__ void mma16816h(float* c, const uint32_t* a, const uint32_t* b) {
    asm volatile("mma.sync.aligned.m16n8k16.row.col.f32.f16.f16.f32 "
        "{%0,%1,%2,%3}, {%4,%5,%6,%7}, {%8,%9}, {%0,%1,%2,%3};"
        : "+f"(c[0]), "+f"(c[1]), "+f"(c[2]), "+f"(c[3])
        : "r"(a[0]), "r"(a[1]), "r"(a[2]), "r"(a[3]), "r"(b[0]), "r"(b[1]));
}
__device__ __forceinline__ uint32_t pkh2(float a, float b) {
    __half2 h = __floats2half2_rn(a, b);
    return *(uint32_t*)&h;
}
#define CPA16(sa, gp) asm volatile("cp.async.cg.shared.global [%0], [%1], 16;" :: "r"(sa), "l"(gp))
#define CP_COMMIT()   asm volatile("cp.async.commit_group;")
#define CP_WAIT0()    asm volatile("cp.async.wait_group 0;" ::: "memory")

// ---------------- fused weight convert + transpose (all 8, fp16 split) ----------------
__global__ void __launch_bounds__(256) cvt_wt_all_kernel(
    const float* __restrict__ W0, const float* __restrict__ W1,
    const float* __restrict__ W2, const float* __restrict__ W3,
    const float* __restrict__ W4, const float* __restrict__ W5,
    const float* __restrict__ W6, const float* __restrict__ W7,
    __half* __restrict__ hi, __half* __restrict__ lo) {
    int w = blockIdx.y;
    const float* W = (w == 0) ? W0 : (w == 1) ? W1 : (w == 2) ? W2 : (w == 3) ? W3 :
                     (w == 4) ? W4 : (w == 5) ? W5 : (w == 6) ? W6 : W7;
    int idx = blockIdx.x * 256 + threadIdx.x;   // idx = n*512 + k
    int n = idx >> 9, k = idx & 511;
    float v = W[k * Dq + n];
    __half h = __float2half_rn(v);
    size_t o = (size_t)w * Dq * Dq + idx;
    hi[o] = h;
    lo[o] = __float2half_rn(v - __half2float(h));
}

// ---------------- positional-embedding add (fp32 + fp16 out) ----------------
__global__ void __launch_bounds__(256) add_pos_kernel(const float* __restrict__ x,
                                                      float* __restrict__ out,
                                                      __half* __restrict__ o16) {
    int idx = blockIdx.x * 256 + threadIdx.x;
    int d = idx & (Dq - 1);
    int s = (idx >> 9) & (Sq - 1);
    float freq  = expf((float)d * -0.0359778920794f);
    float angle = (float)s * freq;
    float pe = (d & 1) ? cosf(angle) : sinf(angle);
    float r = x[idx] + pe;
    out[idx] = r;
    o16[idx] = __float2half_rn(r);
}

// ---------------- fused LayerNorm + residual ----------------
__global__ void __launch_bounds__(256) ln_add_kernel(const float* __restrict__ x,
                                                     const float* __restrict__ gamma,
                                                     const float* __restrict__ beta,
                                                     const float* __restrict__ basep,
                                                     float scale,
                                                     float* __restrict__ out,
                                                     __half* __restrict__ o16) {
    __shared__ float red[256];
    int t = threadIdx.x;
    size_t off = (size_t)blockIdx.x * Dq;

    float v0 = x[off + t];
    float v1 = x[off + t + 256];

    red[t] = v0 + v1;
    __syncthreads();
    #pragma unroll
    for (int s2 = 128; s2 > 0; s2 >>= 1) {
        if (t < s2) red[t] += red[t + s2];
        __syncthreads();
    }
    float mu = red[0] * (1.0f / 512.0f);
    __syncthreads();

    float d0 = v0 - mu, d1 = v1 - mu;
    red[t] = d0 * d0 + d1 * d1;
    __syncthreads();
    #pragma unroll
    for (int s2 = 128; s2 > 0; s2 >>= 1) {
        if (t < s2) red[t] += red[t + s2];
        __syncthreads();
    }
    float var = red[0] * (1.0f / 512.0f);
    float rs  = rsqrtf(var + 1e-3f);

    float r0 = basep[off + t]       + scale * (d0 * rs * gamma[t]       + beta[t]);
    float r1 = basep[off + t + 256] + scale * (d1 * rs * gamma[t + 256] + beta[t + 256]);
    out[off + t]       = r0;
    out[off + t + 256] = r1;
    if (o16) {
        o16[off + t]       = __float2half_rn(r0);
        o16[off + t + 256] = __float2half_rn(r1);
    }
}

// ---------------- GEMM core: fp16 A (single), fp16 split W (2-pass) ----------------
#define APAD 72
#define SA16  0
#define SB_HI 18432
#define SB_LO 27648
#define GEMM_SMEM 36864

struct GemmFrag { float acc[2][4][4]; };

__device__ __forceinline__ void gemm_core(uint32_t sb, char* smem,
                                          const __half* __restrict__ A16,
                                          const __half* __restrict__ Bhi,
                                          const __half* __restrict__ Blo,
                                          int m0, int n0, GemmFrag& F) {
    __half* sA  = (__half*)(smem + SA16);
    __half* sBh = (__half*)(smem + SB_HI);
    __half* sBl = (__half*)(smem + SB_LO);

    int tid = threadIdx.x;
    int wid = tid >> 5, lane = tid & 31;
    int wm = (wid & 3) * 32;
    int wn = (wid >> 2) * 32;

    #pragma unroll
    for (int i = 0; i < 2; i++)
        #pragma unroll
        for (int j = 0; j < 4; j++)
            #pragma unroll
            for (int q = 0; q < 4; q++) F.acc[i][j][q] = 0.0f;

    int la = lane & 15;
    int lacol = (lane >> 4) << 3;
    int lb = lane & 7;
    int lbcol = ((lane >> 3) & 1) << 3;

    for (int kc = 0; kc < 8; kc++) {
        int kofs = kc * 64;
        #pragma unroll
        for (int p = 0; p < 4; p++) {
            int e = tid + p * 256;
            int r = e >> 3, c8 = (e & 7) * 8;
            size_t go = (size_t)(m0 + r) * Dq + kofs + c8;
            *(uint4*)&sA[r * APAD + c8] = *(const uint4*)&A16[go];
        }
        #pragma unroll
        for (int p = 0; p < 2; p++) {
            int e = tid + p * 256;
            int r = e >> 3, c8 = (e & 7) * 8;
            size_t go = (size_t)(n0 + r) * Dq + kofs + c8;
            *(uint4*)&sBh[r * APAD + c8] = *(const uint4*)&Bhi[go];
            *(uint4*)&sBl[r * APAD + c8] = *(const uint4*)&Blo[go];
        }
        __syncthreads();

        #pragma unroll
        for (int ks = 0; ks < 4; ks++) {
            int kk = ks * 16;
            uint32_t a[2][4];
            #pragma unroll
            for (int ma = 0; ma < 2; ma++) {
                int row = wm + ma * 16 + la;
                uint32_t off = (uint32_t)((row * APAD + kk + lacol) * 2);
                ldsm_x4(a[ma], sb + SA16 + off);
            }
            uint32_t bh[4][2], bl[4][2];
            #pragma unroll
            for (int na = 0; na < 4; na++) {
                int rown = wn + na * 8 + lb;
                uint32_t off = (uint32_t)((rown * APAD + kk + lbcol) * 2);
                ldsm_x2(bh[na], sb + SB_HI + off);
                ldsm_x2(bl[na], sb + SB_LO + off);
            }
            #pragma unroll
            for (int ma = 0; ma < 2; ma++)
                #pragma unroll
                for (int na = 0; na < 4; na++) {
                    mma16816h(F.acc[ma][na], a[ma], bh[na]);
                    mma16816h(F.acc[ma][na], a[ma], bl[na]);
                }
        }
        __syncthreads();
    }
}

// ---- generic GEMM: fp32 out (+addend) and/or fp16 out ----
__global__ void __launch_bounds__(256) gemm_mma_kernel(
    const __half* __restrict__ A16,
    const __half* __restrict__ Bhi, const __half* __restrict__ Blo,
    const float* __restrict__ addend, float* __restrict__ C,
    __half* __restrict__ C16) {
    extern __shared__ char smem[];
    uint32_t sb = smem_u32(smem);
    int m0 = blockIdx.y * 128, n0 = blockIdx.x * 64;
    GemmFrag F;
    gemm_core(sb, smem, A16, Bhi, Blo, m0, n0, F);

    int wid = threadIdx.x >> 5, lane = threadIdx.x & 31;
    int wm = (wid & 3) * 32, wn = (wid >> 2) * 32;
    int g = lane >> 2, tq = lane & 3;
    #pragma unroll
    for (int ma = 0; ma < 2; ma++) {
        int row = m0 + wm + ma * 16 + g;
        #pragma unroll
        for (int na = 0; na < 4; na++) {
            int col = n0 + wn + na * 8 + tq * 2;
            size_t o0 = (size_t)row * Dq + col;
            size_t o1 = o0 + 8 * Dq;
            float2 r0 = make_float2(F.acc[ma][na][0], F.acc[ma][na][1]);
            float2 r1 = make_float2(F.acc[ma][na][2], F.acc[ma][na][3]);
            if (addend) {
                float2 a0 = *(const float2*)&addend[o0];
                float2 a1 = *(const float2*)&addend[o1];
                r0.x += a0.x; r0.y += a0.y;
                r1.x += a1.x; r1.y += a1.y;
            }
            if (C) {
                *(float2*)&C[o0] = r0;
                *(float2*)&C[o1] = r1;
            }
            if (C16) {
                *(uint32_t*)&C16[o0] = pkh2(r0.x, r0.y);
                *(uint32_t*)&C16[o1] = pkh2(r1.x, r1.y);
            }
        }
    }
}

// ---- fused QKV GEMM: all outputs fp16 ----
__global__ void __launch_bounds__(256) gemm_qkv_kernel(
    const __half* __restrict__ A16,
    const __half* __restrict__ Whi, const __half* __restrict__ Wlo,
    __half* __restrict__ Q16, __half* __restrict__ K16, __half* __restrict__ V16) {
    extern __shared__ char smem[];
    uint32_t sb = smem_u32(smem);
    int w = blockIdx.x >> 3;                 // 0=Q,1=K,2=V
    int n0 = (blockIdx.x & 7) * 64;
    int m0 = blockIdx.y * 128;
    const __half* Bhi = Whi + (size_t)w * Dq * Dq;
    const __half* Blo = Wlo + (size_t)w * Dq * Dq;
    __half* O16 = (w == 0) ? Q16 : (w == 1) ? K16 : V16;

    GemmFrag F;
    gemm_core(sb, smem, A16, Bhi, Blo, m0, n0, F);

    int wid = threadIdx.x >> 5, lane = threadIdx.x & 31;
    int wm = (wid & 3) * 32, wn = (wid >> 2) * 32;
    int g = lane >> 2, tq = lane & 3;
    #pragma unroll
    for (int ma = 0; ma < 2; ma++) {
        int row = m0 + wm + ma * 16 + g;
        #pragma unroll
        for (int na = 0; na < 4; na++) {
            int col = n0 + wn + na * 8 + tq * 2;
            size_t o0 = (size_t)row * Dq + col;
            size_t o1 = o0 + 8 * Dq;
            *(uint32_t*)&O16[o0] = pkh2(F.acc[ma][na][0], F.acc[ma][na][1]);
            *(uint32_t*)&O16[o1] = pkh2(F.acc[ma][na][2], F.acc[ma][na][3]);
        }
    }
}

// ---------------- flash attention: 128q tiles, all fp16 single-pass ----------------
#define FP 72
#define FQ16 0
#define FKV  18432
#define KK16 0
#define VV16 9216
#define FLASH_SMEM (FKV + 18432)   // 36864

#define LOG2E_DIV_H 0.18033688f    // log2(e)/8

__global__ void __launch_bounds__(256) flash_mma_kernel(
    const __half* __restrict__ Q16,
    const __half* __restrict__ K16,
    const __half* __restrict__ V16,
    float* __restrict__ O,
    __half* __restrict__ O16) {
    extern __shared__ char smem[];
    uint32_t sb = smem_u32(smem);

    int tid = threadIdx.x, wid = tid >> 5, lane = tid & 31;
    int wm = wid * 16;
    int g = lane >> 2, tq = lane & 3;
    int qb = blockIdx.x, h = blockIdx.y, b = blockIdx.z;
    size_t baseQ  = ((size_t)b * Sq + (size_t)qb * 128) * Dq + h * DHq;
    size_t baseKV = (size_t)b * Sq * Dq + h * DHq;

    int rQ = tid >> 1, cQ = (tid & 1) * 32;
    int rK = tid >> 2, cK = (tid & 3) * 16;

    auto kvload = [&](int kb) {
        size_t go = baseKV + (size_t)(kb * 64 + rK) * Dq + cK;
        uint32_t so = sb + FKV + (uint32_t)((rK * FP + cK) * 2);
        #pragma unroll
        for (int q = 0; q < 2; q++) {
            CPA16(so + KK16 + q * 16, &K16[go + q * 8]);
            CPA16(so + VV16 + q * 16, &V16[go + q * 8]);
        }
    };

    {   // Q + KV tile 0
        size_t go = baseQ + (size_t)rQ * Dq + cQ;
        uint32_t so = sb + FQ16 + (uint32_t)((rQ * FP + cQ) * 2);
        #pragma unroll
        for (int q = 0; q < 4; q++)
            CPA16(so + q * 16, &Q16[go + q * 8]);
        kvload(0);
        CP_COMMIT();
        CP_WAIT0();
        __syncthreads();
    }

    float oacc[8][4];
    #pragma unroll
    for (int j = 0; j < 8; j++)
        #pragma unroll
        for (int q = 0; q < 4; q++) oacc[j][q] = 0.0f;
    float mr0 = -1e30f, mr1 = -1e30f, lr0 = 0.0f, lr1 = 0.0f;

    uint32_t aQ = (uint32_t)(((wm + (lane & 15)) * FP + ((lane >> 4) << 3)) * 2);
    uint32_t bK = (uint32_t)(((lane & 7) * FP + (((lane >> 3) & 1) << 3)) * 2);
    uint32_t bV = (uint32_t)(((lane & 15) * FP) * 2);

    for (int kb = 0; kb < 16; kb++) {
        // S = Q @ K^T (single-pass fp16)
        float sacc[8][4];
        #pragma unroll
        for (int j = 0; j < 8; j++)
            #pragma unroll
            for (int q = 0; q < 4; q++) sacc[j][q] = 0.0f;

        #pragma unroll
        for (int ks = 0; ks < 4; ks++) {
            uint32_t aq[4];
            ldsm_x4(aq, sb + FQ16 + aQ + ks * 32);
            #pragma unroll
            for (int na = 0; na < 8; na++) {
                uint32_t bk[2];
                uint32_t off = FKV + KK16 + bK + (uint32_t)(na * 8 * FP * 2) + ks * 32;
                ldsm_x2(bk, sb + off);
                mma16816h(sacc[na], aq, bk);
            }
        }

        // Register softmax in exp2 domain
        float rmax0 = -1e30f, rmax1 = -1e30f;
        #pragma unroll
        for (int j = 0; j < 8; j++) {
            sacc[j][0] *= LOG2E_DIV_H; sacc[j][1] *= LOG2E_DIV_H;
            sacc[j][2] *= LOG2E_DIV_H; sacc[j][3] *= LOG2E_DIV_H;
            rmax0 = fmaxf(rmax0, fmaxf(sacc[j][0], sacc[j][1]));
            rmax1 = fmaxf(rmax1, fmaxf(sacc[j][2], sacc[j][3]));
        }
        rmax0 = fmaxf(rmax0, __shfl_xor_sync(0xffffffffu, rmax0, 1));
        rmax0 = fmaxf(rmax0, __shfl_xor_sync(0xffffffffu, rmax0, 2));
        rmax1 = fmaxf(rmax1, __shfl_xor_sync(0xffffffffu, rmax1, 1));
        rmax1 = fmaxf(rmax1, __shfl_xor_sync(0xffffffffu, rmax1, 2));
        float mn0 = fmaxf(mr0, rmax0), mn1 = fmaxf(mr1, rmax1);
        float al0 = exp2f(mr0 - mn0), al1 = exp2f(mr1 - mn1);
        float sum0 = 0.0f, sum1 = 0.0f;
        #pragma unroll
        for (int j = 0; j < 8; j++) {
            sacc[j][0] = exp2f(sacc[j][0] - mn0);
            sacc[j][1] = exp2f(sacc[j][1] - mn0);
            sacc[j][2] = exp2f(sacc[j][2] - mn1);
            sacc[j][3] = exp2f(sacc[j][3] - mn1);
            sum0 += sacc[j][0] + sacc[j][1];
            sum1 += sacc[j][2] + sacc[j][3];
        }
        sum0 += __shfl_xor_sync(0xffffffffu, sum0, 1);
        sum0 += __shfl_xor_sync(0xffffffffu, sum0, 2);
        sum1 += __shfl_xor_sync(0xffffffffu, sum1, 1);
        sum1 += __shfl_xor_sync(0xffffffffu, sum1, 2);
        lr0 = lr0 * al0 + sum0; mr0 = mn0;
        lr1 = lr1 * al1 + sum1; mr1 = mn1;

        #pragma unroll
        for (int j = 0; j < 8; j++) {
            oacc[j][0] *= al0; oacc[j][1] *= al0;
            oacc[j][2] *= al1; oacc[j][3] *= al1;
        }

        // Re-pack P into fp16 A fragments
        uint32_t ph[4][4];
        #pragma unroll
        for (int k2 = 0; k2 < 4; k2++) {
            ph[k2][0] = pkh2(sacc[2*k2][0],   sacc[2*k2][1]);
            ph[k2][1] = pkh2(sacc[2*k2][2],   sacc[2*k2][3]);
            ph[k2][2] = pkh2(sacc[2*k2+1][0], sacc[2*k2+1][1]);
            ph[k2][3] = pkh2(sacc[2*k2+1][2], sacc[2*k2+1][3]);
        }

        // O += P @ V (single-pass fp16; V via ldmatrix.trans)
        #pragma unroll
        for (int k2 = 0; k2 < 4; k2++) {
            #pragma unroll
            for (int na = 0; na < 8; na++) {
                uint32_t bv[2];
                uint32_t off = FKV + VV16 + bV + (uint32_t)((k2 * 16 * FP + na * 8) * 2);
                ldsm_x2t(bv, sb + off);
                mma16816h(oacc[na], ph[k2], bv);
            }
        }

        // refill single KV buffer for next tile
        __syncthreads();
        if (kb < 15) {
            kvload(kb + 1);
            CP_COMMIT();
            CP_WAIT0();
            __syncthreads();
        }
    }

    float il0 = 1.0f / lr0, il1 = 1.0f / lr1;
    int row0 = wm + g, row1 = wm + g + 8;
    #pragma unroll
    for (int na = 0; na < 8; na++) {
        int col = na * 8 + tq * 2;
        float v00 = oacc[na][0] * il0, v01 = oacc[na][1] * il0;
        float v10 = oacc[na][2] * il1, v11 = oacc[na][3] * il1;
        size_t o0 = baseQ + (size_t)row0 * Dq + col;
        size_t o1 = baseQ + (size_t)row1 * Dq + col;
        if (O) {
            *(float2*)&O[o0] = make_float2(v00, v01);
            *(float2*)&O[o1] = make_float2(v10, v11);
        }
        if (O16) {
            *(uint32_t*)&O16[o0] = pkh2(v00, v01);
            *(uint32_t*)&O16[o1] = pkh2(v10, v11);
        }
    }
}

// ---------------- launcher ----------------
extern "C" void kernel_launch(void* const* d_in, const int* in_sizes, int n_in,
                              void* d_out, int out_size) {
    const float* in0   = (const float*)d_in[0];
    const float* in1   = (const float*)d_in[1];
    const float* ge = (const float*)d_in[6];
    const float* be = (const float*)d_in[7];
    const float* gd = (const float*)d_in[12];
    const float* bd = (const float*)d_in[13];
    float* out = (float*)d_out;

    float *E, *DI, *Sb, *I;
    __half *A16, *Q16, *K16, *V16, *EO16, *Wh, *Wl;
    cudaGetSymbolAddress((void**)&E,    g_E);
    cudaGetSymbolAddress((void**)&DI,   g_DI);
    cudaGetSymbolAddress((void**)&Sb,   g_S);
    cudaGetSymbolAddress((void**)&I,    g_I);
    cudaGetSymbolAddress((void**)&A16,  g_A16);
    cudaGetSymbolAddress((void**)&Q16,  g_Q16);
    cudaGetSymbolAddress((void**)&K16,  g_K16);
    cudaGetSymbolAddress((void**)&V16,  g_V16);
    cudaGetSymbolAddress((void**)&EO16, g_EO16);
    cudaGetSymbolAddress((void**)&Wh,   g_Wh16);
    cudaGetSymbolAddress((void**)&Wl,   g_Wl16);

    cudaFuncSetAttribute(gemm_mma_kernel,  cudaFuncAttributeMaxDynamicSharedMemorySize, GEMM_SMEM);
    cudaFuncSetAttribute(gemm_qkv_kernel,  cudaFuncAttributeMaxDynamicSharedMemorySize, GEMM_SMEM);
    cudaFuncSetAttribute(flash_mma_kernel, cudaFuncAttributeMaxDynamicSharedMemorySize, FLASH_SMEM);

    dim3 ggrid(Dq / 64, BSr / 128);        // (8, 64)
    dim3 qkvgrid(3 * Dq / 64, BSr / 128);  // (24, 64)
    dim3 fgrid(Sq / 128, Hq, Bq);          // (8, 8, 8)
    const int WSZ = Dq * Dq;

    dim3 wgrid(WSZ / 256, 8);
    cvt_wt_all_kernel<<<wgrid, 256>>>(
        (const float*)d_in[2], (const float*)d_in[3], (const float*)d_in[4],
        (const float*)d_in[5], (const float*)d_in[8], (const float*)d_in[9],
        (const float*)d_in[10], (const float*)d_in[11], Wh, Wl);

    // ---- Encoder ----
    add_pos_kernel<<<BSD / 256, 256>>>(in0, E, A16);
    gemm_qkv_kernel<<<qkvgrid, 256, GEMM_SMEM>>>(A16, Wh, Wl, Q16, K16, V16);
    flash_mma_kernel<<<fgrid, 256, FLASH_SMEM>>>(Q16, K16, V16, Sb, nullptr);
    ln_add_kernel<<<BSr, 256>>>(Sb, ge, be, E, 1.0f, I, A16);
    gemm_mma_kernel<<<ggrid, 256, GEMM_SMEM>>>(A16, Wh + 3 * WSZ, Wl + 3 * WSZ,
                                               E, nullptr, EO16);          // enc_out (fp16 only)

    // ---- Decoder ----
    add_pos_kernel<<<BSD / 256, 256>>>(in1, DI, A16);
    gemm_qkv_kernel<<<qkvgrid, 256, GEMM_SMEM>>>(A16, Wh + 4 * WSZ, Wl + 4 * WSZ,
                                                 Q16, K16, V16);
    flash_mma_kernel<<<fgrid, 256, FLASH_SMEM>>>(Q16, K16, V16, Sb, nullptr);
    ln_add_kernel<<<BSr, 256>>>(Sb, gd, bd, DI, 2.0f, I, nullptr);         // i2
    flash_mma_kernel<<<fgrid, 256, FLASH_SMEM>>>(EO16, EO16, EO16, nullptr, A16);  // eda
    gemm_mma_kernel<<<ggrid, 256, GEMM_SMEM>>>(A16, Wh + 7 * WSZ, Wl + 7 * WSZ,
                                               I, out, nullptr);           // dec_out
}

// round 12
// speedup vs baseline: 2.1749x; 1.1695x over previous
#include <cuda_runtime.h>
#include <cuda_bf16.h>
#include <cuda_fp16.h>
#include <cstdint>
#include <math.h>

// Problem constants
#define Bq   8
#define Sq   1024
#define Dq   512
#define Hq   8
#define DHq  64
#define BSr  (Bq*Sq)        // 8192 rows
#define BSD  (Bq*Sq*Dq)     // 4194304 elements

// ---------------- device scratch (no allocations allowed) ----------------
__device__ float g_E [BSD];
__device__ float g_DI[BSD];
__device__ float g_S [BSD];
__device__ float g_I [BSD];
__device__ __half g_A16[BSD];
__device__ __half g_Q16[BSD];
__device__ __half g_K16[BSD];
__device__ __half g_V16[BSD];
__device__ __half g_EO16[BSD];
__device__ __half g_W16[8 * Dq * Dq];   // transposed weights [n][k], fp16

// ---------------- helpers (non-'a' ISA only) ----------------
__device__ __forceinline__ uint32_t smem_u32(const void* p) {
    uint32_t a;
    asm("{ .reg .u64 t; cvta.to.shared.u64 t, %1; cvt.u32.u64 %0, t; }" : "=r"(a) : "l"(p));
    return a;
}
__device__ __forceinline__ void ldsm_x4(uint32_t* r, uint32_t addr) {
    asm volatile("ldmatrix.sync.aligned.m8n8.x4.shared.b16 {%0,%1,%2,%3}, [%4];"
        : "=r"(r[0]), "=r"(r[1]), "=r"(r[2]), "=r"(r[3]) : "r"(addr));
}
__device__ __forceinline__ void ldsm_x2(uint32_t* r, uint32_t addr) {
    asm volatile("ldmatrix.sync.aligned.m8n8.x2.shared.b16 {%0,%1}, [%2];"
        : "=r"(r[0]), "=r"(r[1]) : "r"(addr));
}
__device__ __forceinline__ void ldsm_x2t(uint32_t* r, uint32_t addr) {
    asm volatile("ldmatrix.sync.aligned.m8n8.x2.trans.shared.b16 {%0,%1}, [%2];"
        : "=r"(r[0]), "=r"(r[1]) : "r"(addr));
}
__device__ __forceinline__ void mma16816h(float* c, const uint32_t* a, const uint32_t* b) {
    asm volatile("mma.sync.aligned.m16n8k16.row.col.f32.f16.f16.f32 "
        "{%0,%1,%2,%3}, {%4,%5,%6,%7}, {%8,%9}, {%0,%1,%2,%3};"
        : "+f"(c[0]), "+f"(c[1]), "+f"(c[2]), "+f"(c[3])
        : "r"(a[0]), "r"(a[1]), "r"(a[2]), "r"(a[3]), "r"(b[0]), "r"(b[1]));
}
__device__ __forceinline__ uint32_t pkh2(float a, float b) {
    __half2 h = __floats2half2_rn(a, b);
    return *(uint32_t*)&h;
}
#define CPA16(sa, gp) asm volatile("cp.async.cg.shared.global [%0], [%1], 16;" :: "r"(sa), "l"(gp))
#define CP_COMMIT()   asm volatile("cp.async.commit_group;")
#define CP_WAIT0()    asm volatile("cp.async.wait_group 0;" ::: "memory")

// ---------------- fused weight convert + transpose (all 8, fp16) ----------------
__global__ void __launch_bounds__(256) cvt_wt_all_kernel(
    const float* __restrict__ W0, const float* __restrict__ W1,
    const float* __restrict__ W2, const float* __restrict__ W3,
    const float* __restrict__ W4, const float* __restrict__ W5,
    const float* __restrict__ W6, const float* __restrict__ W7,
    __half* __restrict__ o16) {
    int w = blockIdx.y;
    const float* W = (w == 0) ? W0 : (w == 1) ? W1 : (w == 2) ? W2 : (w == 3) ? W3 :
                     (w == 4) ? W4 : (w == 5) ? W5 : (w == 6) ? W6 : W7;
    int idx = blockIdx.x * 256 + threadIdx.x;   // idx = n*512 + k
    int n = idx >> 9, k = idx & 511;
    o16[(size_t)w * Dq * Dq + idx] = __float2half_rn(W[k * Dq + n]);
}

// ---------------- positional-embedding add (fp32 + fp16 out) ----------------
__global__ void __launch_bounds__(256) add_pos_kernel(const float* __restrict__ x,
                                                      float* __restrict__ out,
                                                      __half* __restrict__ o16) {
    int idx = blockIdx.x * 256 + threadIdx.x;
    int d = idx & (Dq - 1);
    int s = (idx >> 9) & (Sq - 1);
    float freq  = expf((float)d * -0.0359778920794f);
    float angle = (float)s * freq;
    float pe = (d & 1) ? cosf(angle) : sinf(angle);
    float r = x[idx] + pe;
    out[idx] = r;
    o16[idx] = __float2half_rn(r);
}

// ---------------- fused LayerNorm + residual ----------------
__global__ void __launch_bounds__(256) ln_add_kernel(const float* __restrict__ x,
                                                     const float* __restrict__ gamma,
                                                     const float* __restrict__ beta,
                                                     const float* __restrict__ basep,
                                                     float scale,
                                                     float* __restrict__ out,
                                                     __half* __restrict__ o16) {
    __shared__ float red[256];
    int t = threadIdx.x;
    size_t off = (size_t)blockIdx.x * Dq;

    float v0 = x[off + t];
    float v1 = x[off + t + 256];

    red[t] = v0 + v1;
    __syncthreads();
    #pragma unroll
    for (int s2 = 128; s2 > 0; s2 >>= 1) {
        if (t < s2) red[t] += red[t + s2];
        __syncthreads();
    }
    float mu = red[0] * (1.0f / 512.0f);
    __syncthreads();

    float d0 = v0 - mu, d1 = v1 - mu;
    red[t] = d0 * d0 + d1 * d1;
    __syncthreads();
    #pragma unroll
    for (int s2 = 128; s2 > 0; s2 >>= 1) {
        if (t < s2) red[t] += red[t + s2];
        __syncthreads();
    }
    float var = red[0] * (1.0f / 512.0f);
    float rs  = rsqrtf(var + 1e-3f);

    float r0 = basep[off + t]       + scale * (d0 * rs * gamma[t]       + beta[t]);
    float r1 = basep[off + t + 256] + scale * (d1 * rs * gamma[t + 256] + beta[t + 256]);
    out[off + t]       = r0;
    out[off + t + 256] = r1;
    if (o16) {
        o16[off + t]       = __float2half_rn(r0);
        o16[off + t + 256] = __float2half_rn(r1);
    }
}

// ---------------- GEMM core: fp16 A x fp16 W, single pass ----------------
#define APAD 72
#define SA16 0
#define SB16 18432
#define GEMM_SMEM 27648

struct GemmFrag { float acc[2][4][4]; };

__device__ __forceinline__ void gemm_core(uint32_t sb, char* smem,
                                          const __half* __restrict__ A16,
                                          const __half* __restrict__ B16,
                                          int m0, int n0, GemmFrag& F) {
    __half* sA = (__half*)(smem + SA16);
    __half* sB = (__half*)(smem + SB16);

    int tid = threadIdx.x;
    int wid = tid >> 5, lane = tid & 31;
    int wm = (wid & 3) * 32;
    int wn = (wid >> 2) * 32;

    #pragma unroll
    for (int i = 0; i < 2; i++)
        #pragma unroll
        for (int j = 0; j < 4; j++)
            #pragma unroll
            for (int q = 0; q < 4; q++) F.acc[i][j][q] = 0.0f;

    int la = lane & 15;
    int lacol = (lane >> 4) << 3;
    int lb = lane & 7;
    int lbcol = ((lane >> 3) & 1) << 3;

    for (int kc = 0; kc < 8; kc++) {
        int kofs = kc * 64;
        #pragma unroll
        for (int p = 0; p < 4; p++) {
            int e = tid + p * 256;
            int r = e >> 3, c8 = (e & 7) * 8;
            size_t go = (size_t)(m0 + r) * Dq + kofs + c8;
            *(uint4*)&sA[r * APAD + c8] = *(const uint4*)&A16[go];
        }
        #pragma unroll
        for (int p = 0; p < 2; p++) {
            int e = tid + p * 256;
            int r = e >> 3, c8 = (e & 7) * 8;
            size_t go = (size_t)(n0 + r) * Dq + kofs + c8;
            *(uint4*)&sB[r * APAD + c8] = *(const uint4*)&B16[go];
        }
        __syncthreads();

        #pragma unroll
        for (int ks = 0; ks < 4; ks++) {
            int kk = ks * 16;
            uint32_t a[2][4];
            #pragma unroll
            for (int ma = 0; ma < 2; ma++) {
                int row = wm + ma * 16 + la;
                uint32_t off = (uint32_t)((row * APAD + kk + lacol) * 2);
                ldsm_x4(a[ma], sb + SA16 + off);
            }
            uint32_t bfr[4][2];
            #pragma unroll
            for (int na = 0; na < 4; na++) {
                int rown = wn + na * 8 + lb;
                uint32_t off = (uint32_t)((rown * APAD + kk + lbcol) * 2);
                ldsm_x2(bfr[na], sb + SB16 + off);
            }
            #pragma unroll
            for (int ma = 0; ma < 2; ma++)
                #pragma unroll
                for (int na = 0; na < 4; na++)
                    mma16816h(F.acc[ma][na], a[ma], bfr[na]);
        }
        __syncthreads();
    }
}

// ---- generic GEMM: fp32 out (+addend) and/or fp16 out ----
__global__ void __launch_bounds__(256) gemm_mma_kernel(
    const __half* __restrict__ A16, const __half* __restrict__ B16,
    const float* __restrict__ addend, float* __restrict__ C,
    __half* __restrict__ C16) {
    extern __shared__ char smem[];
    uint32_t sb = smem_u32(smem);
    int m0 = blockIdx.y * 128, n0 = blockIdx.x * 64;
    GemmFrag F;
    gemm_core(sb, smem, A16, B16, m0, n0, F);

    int wid = threadIdx.x >> 5, lane = threadIdx.x & 31;
    int wm = (wid & 3) * 32, wn = (wid >> 2) * 32;
    int g = lane >> 2, tq = lane & 3;
    #pragma unroll
    for (int ma = 0; ma < 2; ma++) {
        int row = m0 + wm + ma * 16 + g;
        #pragma unroll
        for (int na = 0; na < 4; na++) {
            int col = n0 + wn + na * 8 + tq * 2;
            size_t o0 = (size_t)row * Dq + col;
            size_t o1 = o0 + 8 * Dq;
            float2 r0 = make_float2(F.acc[ma][na][0], F.acc[ma][na][1]);
            float2 r1 = make_float2(F.acc[ma][na][2], F.acc[ma][na][3]);
            if (addend) {
                float2 a0 = *(const float2*)&addend[o0];
                float2 a1 = *(const float2*)&addend[o1];
                r0.x += a0.x; r0.y += a0.y;
                r1.x += a1.x; r1.y += a1.y;
            }
            if (C) {
                *(float2*)&C[o0] = r0;
                *(float2*)&C[o1] = r1;
            }
            if (C16) {
                *(uint32_t*)&C16[o0] = pkh2(r0.x, r0.y);
                *(uint32_t*)&C16[o1] = pkh2(r1.x, r1.y);
            }
        }
    }
}

// ---- fused QKV GEMM: all outputs fp16 ----
__global__ void __launch_bounds__(256) gemm_qkv_kernel(
    const __half* __restrict__ A16, const __half* __restrict__ W16,
    __half* __restrict__ Q16, __half* __restrict__ K16, __half* __restrict__ V16) {
    extern __shared__ char smem[];
    uint32_t sb = smem_u32(smem);
    int w = blockIdx.x >> 3;                 // 0=Q,1=K,2=V
    int n0 = (blockIdx.x & 7) * 64;
    int m0 = blockIdx.y * 128;
    const __half* B16 = W16 + (size_t)w * Dq * Dq;
    __half* O16 = (w == 0) ? Q16 : (w == 1) ? K16 : V16;

    GemmFrag F;
    gemm_core(sb, smem, A16, B16, m0, n0, F);

    int wid = threadIdx.x >> 5, lane = threadIdx.x & 31;
    int wm = (wid & 3) * 32, wn = (wid >> 2) * 32;
    int g = lane >> 2, tq = lane & 3;
    #pragma unroll
    for (int ma = 0; ma < 2; ma++) {
        int row = m0 + wm + ma * 16 + g;
        #pragma unroll
        for (int na = 0; na < 4; na++) {
            int col = n0 + wn + na * 8 + tq * 2;
            size_t o0 = (size_t)row * Dq + col;
            size_t o1 = o0 + 8 * Dq;
            *(uint32_t*)&O16[o0] = pkh2(F.acc[ma][na][0], F.acc[ma][na][1]);
            *(uint32_t*)&O16[o1] = pkh2(F.acc[ma][na][2], F.acc[ma][na][3]);
        }
    }
}

// ---------------- flash attention: 128q tiles, fp16, KV double-buffered ----------------
#define FP 72
#define FQ16 0
#define FKV  18432
#define KK16 0
#define VV16 9216
#define KVBUF 18432
#define FLASH_SMEM (FKV + 2 * KVBUF)   // 55296 -> 2 CTAs/SM

#define LOG2E_DIV_H 0.18033688f    // log2(e)/8

__global__ void __launch_bounds__(256) flash_mma_kernel(
    const __half* __restrict__ Q16,
    const __half* __restrict__ K16,
    const __half* __restrict__ V16,
    float* __restrict__ O,
    __half* __restrict__ O16) {
    extern __shared__ char smem[];
    uint32_t sb = smem_u32(smem);

    int tid = threadIdx.x, wid = tid >> 5, lane = tid & 31;
    int wm = wid * 16;
    int g = lane >> 2, tq = lane & 3;
    int qb = blockIdx.x, h = blockIdx.y, b = blockIdx.z;
    size_t baseQ  = ((size_t)b * Sq + (size_t)qb * 128) * Dq + h * DHq;
    size_t baseKV = (size_t)b * Sq * Dq + h * DHq;

    int rQ = tid >> 1, cQ = (tid & 1) * 32;
    int rK = tid >> 2, cK = (tid & 3) * 16;

    auto kvload = [&](int kb, uint32_t bofs) {
        size_t go = baseKV + (size_t)(kb * 64 + rK) * Dq + cK;
        uint32_t so = sb + FKV + bofs + (uint32_t)((rK * FP + cK) * 2);
        #pragma unroll
        for (int q = 0; q < 2; q++) {
            CPA16(so + KK16 + q * 16, &K16[go + q * 8]);
            CPA16(so + VV16 + q * 16, &V16[go + q * 8]);
        }
    };

    {   // Q + KV tile 0
        size_t go = baseQ + (size_t)rQ * Dq + cQ;
        uint32_t so = sb + FQ16 + (uint32_t)((rQ * FP + cQ) * 2);
        #pragma unroll
        for (int q = 0; q < 4; q++)
            CPA16(so + q * 16, &Q16[go + q * 8]);
        kvload(0, 0);
        CP_COMMIT();
        CP_WAIT0();
        __syncthreads();
    }

    float oacc[8][4];
    #pragma unroll
    for (int j = 0; j < 8; j++)
        #pragma unroll
        for (int q = 0; q < 4; q++) oacc[j][q] = 0.0f;
    float mr0 = -1e30f, mr1 = -1e30f, lr0 = 0.0f, lr1 = 0.0f;

    uint32_t aQ = (uint32_t)(((wm + (lane & 15)) * FP + ((lane >> 4) << 3)) * 2);
    uint32_t bK = (uint32_t)(((lane & 7) * FP + (((lane >> 3) & 1) << 3)) * 2);
    uint32_t bV = (uint32_t)(((lane & 15) * FP) * 2);

    for (int kb = 0; kb < 16; kb++) {
        uint32_t cur = FKV + ((kb & 1) ? KVBUF : 0);
        if (kb < 15) {
            kvload(kb + 1, (kb & 1) ? 0 : KVBUF);   // prefetch into other buffer
            CP_COMMIT();
        }

        // S = Q @ K^T (single-pass fp16)
        float sacc[8][4];
        #pragma unroll
        for (int j = 0; j < 8; j++)
            #pragma unroll
            for (int q = 0; q < 4; q++) sacc[j][q] = 0.0f;

        #pragma unroll
        for (int ks = 0; ks < 4; ks++) {
            uint32_t aq[4];
            ldsm_x4(aq, sb + FQ16 + aQ + ks * 32);
            #pragma unroll
            for (int na = 0; na < 8; na++) {
                uint32_t bk[2];
                uint32_t off = cur + KK16 + bK + (uint32_t)(na * 8 * FP * 2) + ks * 32;
                ldsm_x2(bk, sb + off);
                mma16816h(sacc[na], aq, bk);
            }
        }

        // Register softmax in exp2 domain
        float rmax0 = -1e30f, rmax1 = -1e30f;
        #pragma unroll
        for (int j = 0; j < 8; j++) {
            sacc[j][0] *= LOG2E_DIV_H; sacc[j][1] *= LOG2E_DIV_H;
            sacc[j][2] *= LOG2E_DIV_H; sacc[j][3] *= LOG2E_DIV_H;
            rmax0 = fmaxf(rmax0, fmaxf(sacc[j][0], sacc[j][1]));
            rmax1 = fmaxf(rmax1, fmaxf(sacc[j][2], sacc[j][3]));
        }
        rmax0 = fmaxf(rmax0, __shfl_xor_sync(0xffffffffu, rmax0, 1));
        rmax0 = fmaxf(rmax0, __shfl_xor_sync(0xffffffffu, rmax0, 2));
        rmax1 = fmaxf(rmax1, __shfl_xor_sync(0xffffffffu, rmax1, 1));
        rmax1 = fmaxf(rmax1, __shfl_xor_sync(0xffffffffu, rmax1, 2));
        float mn0 = fmaxf(mr0, rmax0), mn1 = fmaxf(mr1, rmax1);
        float al0 = exp2f(mr0 - mn0), al1 = exp2f(mr1 - mn1);
        float sum0 = 0.0f, sum1 = 0.0f;
        #pragma unroll
        for (int j = 0; j < 8; j++) {
            sacc[j][0] = exp2f(sacc[j][0] - mn0);
            sacc[j][1] = exp2f(sacc[j][1] - mn0);
            sacc[j][2] = exp2f(sacc[j][2] - mn1);
            sacc[j][3] = exp2f(sacc[j][3] - mn1);
            sum0 += sacc[j][0] + sacc[j][1];
            sum1 += sacc[j][2] + sacc[j][3];
        }
        sum0 += __shfl_xor_sync(0xffffffffu, sum0, 1);
        sum0 += __shfl_xor_sync(0xffffffffu, sum0, 2);
        sum1 += __shfl_xor_sync(0xffffffffu, sum1, 1);
        sum1 += __shfl_xor_sync(0xffffffffu, sum1, 2);
        lr0 = lr0 * al0 + sum0; mr0 = mn0;
        lr1 = lr1 * al1 + sum1; mr1 = mn1;

        #pragma unroll
        for (int j = 0; j < 8; j++) {
            oacc[j][0] *= al0; oacc[j][1] *= al0;
            oacc[j][2] *= al1; oacc[j][3] *= al1;
        }

        // Re-pack P into fp16 A fragments
        uint32_t ph[4][4];
        #pragma unroll
        for (int k2 = 0; k2 < 4; k2++) {
            ph[k2][0] = pkh2(sacc[2*k2][0],   sacc[2*k2][1]);
            ph[k2][1] = pkh2(sacc[2*k2][2],   sacc[2*k2][3]);
            ph[k2][2] = pkh2(sacc[2*k2+1][0], sacc[2*k2+1][1]);
            ph[k2][3] = pkh2(sacc[2*k2+1][2], sacc[2*k2+1][3]);
        }

        // O += P @ V (single-pass fp16; V via ldmatrix.trans)
        #pragma unroll
        for (int k2 = 0; k2 < 4; k2++) {
            #pragma unroll
            for (int na = 0; na < 8; na++) {
                uint32_t bv[2];
                uint32_t off = cur + VV16 + bV + (uint32_t)((k2 * 16 * FP + na * 8) * 2);
                ldsm_x2t(bv, sb + off);
                mma16816h(oacc[na], ph[k2], bv);
            }
        }

        // wait for the prefetch, then barrier so no warp reads a half-filled buffer
        if (kb < 15) CP_WAIT0();
        __syncthreads();
    }

    float il0 = 1.0f / lr0, il1 = 1.0f / lr1;
    int row0 = wm + g, row1 = wm + g + 8;
    #pragma unroll
    for (int na = 0; na < 8; na++) {
        int col = na * 8 + tq * 2;
        float v00 = oacc[na][0] * il0, v01 = oacc[na][1] * il0;
        float v10 = oacc[na][2] * il1, v11 = oacc[na][3] * il1;
        size_t o0 = baseQ + (size_t)row0 * Dq + col;
        size_t o1 = baseQ + (size_t)row1 * Dq + col;
        if (O) {
            *(float2*)&O[o0] = make_float2(v00, v01);
            *(float2*)&O[o1] = make_float2(v10, v11);
        }
        if (O16) {
            *(uint32_t*)&O16[o0] = pkh2(v00, v01);
            *(uint32_t*)&O16[o1] = pkh2(v10, v11);
        }
    }
}

// ---------------- launcher ----------------
extern "C" void kernel_launch(void* const* d_in, const int* in_sizes, int n_in,
                              void* d_out, int out_size) {
    const float* in0   = (const float*)d_in[0];
    const float* in1   = (const float*)d_in[1];
    const float* ge = (const float*)d_in[6];
    const float* be = (const float*)d_in[7];
    const float* gd = (const float*)d_in[12];
    const float* bd = (const float*)d_in[13];
    float* out = (float*)d_out;

    float *E, *DI, *Sb, *I;
    __half *A16, *Q16, *K16, *V16, *EO16, *W16;
    cudaGetSymbolAddress((void**)&E,    g_E);
    cudaGetSymbolAddress((void**)&DI,   g_DI);
    cudaGetSymbolAddress((void**)&Sb,   g_S);
    cudaGetSymbolAddress((void**)&I,    g_I);
    cudaGetSymbolAddress((void**)&A16,  g_A16);
    cudaGetSymbolAddress((void**)&Q16,  g_Q16);
    cudaGetSymbolAddress((void**)&K16,  g_K16);
    cudaGetSymbolAddress((void**)&V16,  g_V16);
    cudaGetSymbolAddress((void**)&EO16, g_EO16);
    cudaGetSymbolAddress((void**)&W16,  g_W16);

    cudaFuncSetAttribute(gemm_mma_kernel,  cudaFuncAttributeMaxDynamicSharedMemorySize, GEMM_SMEM);
    cudaFuncSetAttribute(gemm_qkv_kernel,  cudaFuncAttributeMaxDynamicSharedMemorySize, GEMM_SMEM);
    cudaFuncSetAttribute(flash_mma_kernel, cudaFuncAttributeMaxDynamicSharedMemorySize, FLASH_SMEM);

    dim3 ggrid(Dq / 64, BSr / 128);        // (8, 64)
    dim3 qkvgrid(3 * Dq / 64, BSr / 128);  // (24, 64)
    dim3 fgrid(Sq / 128, Hq, Bq);          // (8, 8, 8)
    const int WSZ = Dq * Dq;

    dim3 wgrid(WSZ / 256, 8);
    cvt_wt_all_kernel<<<wgrid, 256>>>(
        (const float*)d_in[2], (const float*)d_in[3], (const float*)d_in[4],
        (const float*)d_in[5], (const float*)d_in[8], (const float*)d_in[9],
        (const float*)d_in[10], (const float*)d_in[11], W16);

    // ---- Encoder ----
    add_pos_kernel<<<BSD / 256, 256>>>(in0, E, A16);
    gemm_qkv_kernel<<<qkvgrid, 256, GEMM_SMEM>>>(A16, W16, Q16, K16, V16);
    flash_mma_kernel<<<fgrid, 256, FLASH_SMEM>>>(Q16, K16, V16, Sb, nullptr);
    ln_add_kernel<<<BSr, 256>>>(Sb, ge, be, E, 1.0f, I, A16);
    gemm_mma_kernel<<<ggrid, 256, GEMM_SMEM>>>(A16, W16 + 3 * WSZ,
                                               E, nullptr, EO16);          // enc_out (fp16 only)

    // ---- Decoder ----
    add_pos_kernel<<<BSD / 256, 256>>>(in1, DI, A16);
    gemm_qkv_kernel<<<qkvgrid, 256, GEMM_SMEM>>>(A16, W16 + 4 * WSZ, Q16, K16, V16);
    flash_mma_kernel<<<fgrid, 256, FLASH_SMEM>>>(Q16, K16, V16, Sb, nullptr);
    ln_add_kernel<<<BSr, 256>>>(Sb, gd, bd, DI, 2.0f, I, nullptr);         // i2
    flash_mma_kernel<<<fgrid, 256, FLASH_SMEM>>>(EO16, EO16, EO16, nullptr, A16);  // eda
    gemm_mma_kernel<<<ggrid, 256, GEMM_SMEM>>>(A16, W16 + 7 * WSZ,
                                               I, out, nullptr);           // dec_out
}